// round 5
// baseline (speedup 1.0000x reference)
#include <cuda_runtime.h>
#include <cuda_bf16.h>
#include <cstdint>

#define N_NODES 30000
#define N_PAD   30080      // 235 * 128
#define N_EDGES 480000
#define DIN     1000
#define KSEC    1024       // padded section K
#define KTOT    3072       // 3 sections
#define NH      8
#define FH      32
#define HF      256        // NH*FH
#define DEMB    64
#define NEG     0.2f

// ---------------- scratch (device globals; no allocation allowed) ----------
__device__ __nv_bfloat16 g_xhi[(size_t)N_PAD*KSEC];
__device__ __nv_bfloat16 g_xlo[(size_t)N_PAD*KSEC];
__device__ __nv_bfloat16 g_wB [(size_t)HF*KTOT];    // B' [N=256][K=3072] K-major
__device__ float g_h   [(size_t)N_NODES*HF];   // x@W
__device__ float g_as  [N_NODES*NH];
__device__ float g_ad  [N_NODES*NH];
__device__ int   g_deg [N_NODES];
__device__ int   g_off [N_NODES+1];
__device__ int   g_cur [N_NODES];
__device__ int   g_srcs[N_EDGES];              // src ids sorted by dst
__device__ float g_gat [(size_t)N_NODES*HF];   // relu(GAT out + bias)
__device__ float g_d   [(size_t)N_NODES*FH];   // decoder hidden

// ======================= helpers ============================================
__device__ __forceinline__ uint32_t smem_to_u32(const void* p) {
    uint32_t a;
    asm("{ .reg .u64 t; cvta.to.shared.u64 t, %1; cvt.u32.u64 %0, t; }"
        : "=r"(a) : "l"(p));
    return a;
}
__device__ __forceinline__ void cpasync16(uint32_t saddr, const void* gp) {
    asm volatile("cp.async.cg.shared.global [%0], [%1], 16;" :: "r"(saddr), "l"(gp));
}
__device__ __forceinline__ void ldm_x4(uint32_t& r0, uint32_t& r1,
                                       uint32_t& r2, uint32_t& r3, uint32_t a) {
    asm volatile("ldmatrix.sync.aligned.m8n8.x4.shared.b16 {%0,%1,%2,%3}, [%4];"
                 : "=r"(r0), "=r"(r1), "=r"(r2), "=r"(r3) : "r"(a));
}
__device__ __forceinline__ void mma_bf16(float* c, const uint32_t* a,
                                         uint32_t b0, uint32_t b1) {
    asm volatile(
        "mma.sync.aligned.m16n8k16.row.col.f32.bf16.bf16.f32 "
        "{%0,%1,%2,%3}, {%4,%5,%6,%7}, {%8,%9}, {%0,%1,%2,%3};"
        : "+f"(c[0]), "+f"(c[1]), "+f"(c[2]), "+f"(c[3])
        : "r"(a[0]), "r"(a[1]), "r"(a[2]), "r"(a[3]), "r"(b0), "r"(b1));
}

// ======================= split / pack kernels ===============================
__global__ void split_x_kernel(const float* __restrict__ x) {
    size_t idx = (size_t)blockIdx.x * blockDim.x + threadIdx.x;
    if (idx >= (size_t)N_PAD * KSEC) return;
    int r = (int)(idx >> 10);
    int c = (int)(idx & 1023);
    float v = (r < N_NODES && c < DIN) ? x[(size_t)r * DIN + c] : 0.f;
    __nv_bfloat16 hi = __float2bfloat16(v);
    g_xhi[idx] = hi;
    g_xlo[idx] = __float2bfloat16(v - __bfloat162float(hi));
}
__global__ void build_wB_kernel(const float* __restrict__ W) {
    int idx = blockIdx.x * blockDim.x + threadIdx.x;       // over 256*3072
    if (idx >= HF * KTOT) return;
    int n  = idx / KTOT;
    int kk = idx % KTOT;
    int s  = kk >> 10;
    int k  = kk & 1023;
    float v = (k < DIN) ? W[(size_t)k * HF + n] : 0.f;
    __nv_bfloat16 hi = __float2bfloat16(v);
    g_wB[idx] = (s == 2) ? __float2bfloat16(v - __bfloat162float(hi)) : hi;
}

// ======================= bf16 mma.sync GEMM1 ================================
// C[30080,256] = A'[30080,3072]bf16 @ B'[3072,256]bf16 (B stored [256][3072])
// BM=128 BN=256 BK=32, 256 threads, 8 warps (2 m x 4 n), warp tile 64x64.
#define BKC  32
#define LDSM 40           // BKC + 8 pad elements (80B row stride)
#define NCH  96           // 3072/32
#define ASZ  10240u       // 128*40*2 bytes per A stage
#define BSZ  20480u       // 256*40*2 bytes per B stage
#define GSMT (2u*(ASZ+BSZ))   // 61440 dynamic smem

__global__ void __launch_bounds__(256, 1) gemm1_mma_kernel() {
    extern __shared__ char smem[];
    const uint32_t sb = smem_to_u32(smem);
    const int t    = threadIdx.x;
    const int lane = t & 31;
    const int wid  = t >> 5;
    const int wm   = (wid & 1) * 64;
    const int wn   = (wid >> 1) * 64;
    const int m0   = blockIdx.x * 128;

    float acc[4][8][4];
    #pragma unroll
    for (int i = 0; i < 4; i++)
        #pragma unroll
        for (int j = 0; j < 8; j++)
            #pragma unroll
            for (int q = 0; q < 4; q++) acc[i][j][q] = 0.f;

    // A-frag ldmatrix row/col (within warp tile)
    const int a_r = (lane & 7) + ((lane >> 3) & 1) * 8;
    const int a_c = (lane >> 4) * 8;
    // B-frag ldmatrix row/col
    const int b_r = ((lane >> 4) & 1) * 8 + (lane & 7);
    const int b_c = ((lane >> 3) & 1) * 8;

    auto sAaddr = [&](int s, int r, int c) -> uint32_t {
        return sb + (uint32_t)s * ASZ + (uint32_t)r * (LDSM * 2) + (uint32_t)c * 2;
    };
    auto sBaddr = [&](int s, int r, int c) -> uint32_t {
        return sb + 2u * ASZ + (uint32_t)s * BSZ + (uint32_t)r * (LDSM * 2) + (uint32_t)c * 2;
    };

    // stage: A 128x32 (512 chunks of 16B), B 256x32 (1024 chunks of 16B)
    auto load_stage = [&](int s, int c) {
        const int kp  = c * BKC;
        const int sec = kp >> 10;
        const int ko  = kp & 1023;
        const __nv_bfloat16* Abase = ((sec == 1) ? g_xlo : g_xhi)
                                     + (size_t)m0 * KSEC + ko;
        const __nv_bfloat16* Bbase = g_wB + kp;
        #pragma unroll
        for (int i = 0; i < 2; i++) {
            int u  = t + 256 * i;
            int r  = u >> 2;            // 0..127
            int ch = (u & 3) * 8;       // 0,8,16,24
            cpasync16(sAaddr(s, r, ch), Abase + (size_t)r * KSEC + ch);
        }
        #pragma unroll
        for (int i = 0; i < 4; i++) {
            int u  = t + 256 * i;
            int r  = u >> 2;            // 0..255
            int ch = (u & 3) * 8;
            cpasync16(sBaddr(s, r, ch), Bbase + (size_t)r * KTOT + ch);
        }
    };

    load_stage(0, 0);
    asm volatile("cp.async.commit_group;" ::: "memory");
    load_stage(1, 1);
    asm volatile("cp.async.commit_group;" ::: "memory");

    for (int c = 0; c < NCH; c++) {
        const int s = c & 1;
        asm volatile("cp.async.wait_group 1;" ::: "memory");
        __syncthreads();

        #pragma unroll
        for (int ks = 0; ks < 2; ks++) {
            const int kb = ks * 16;
            uint32_t a[4][4];
            #pragma unroll
            for (int mt = 0; mt < 4; mt++)
                ldm_x4(a[mt][0], a[mt][1], a[mt][2], a[mt][3],
                       sAaddr(s, wm + mt * 16 + a_r, kb + a_c));
            #pragma unroll
            for (int nt4 = 0; nt4 < 4; nt4++) {
                uint32_t b0, b1, b2, b3;
                ldm_x4(b0, b1, b2, b3, sBaddr(s, wn + nt4 * 16 + b_r, kb + b_c));
                #pragma unroll
                for (int mt = 0; mt < 4; mt++) {
                    mma_bf16(acc[mt][nt4 * 2 + 0], a[mt], b0, b1);
                    mma_bf16(acc[mt][nt4 * 2 + 1], a[mt], b2, b3);
                }
            }
        }
        __syncthreads();
        if (c + 2 < NCH) load_stage(s, c + 2);
        asm volatile("cp.async.commit_group;" ::: "memory");
    }

    // epilogue: write C fragments to g_h
    #pragma unroll
    for (int mt = 0; mt < 4; mt++) {
        const int r0 = m0 + wm + mt * 16 + (lane >> 2);
        #pragma unroll
        for (int nt = 0; nt < 8; nt++) {
            const int cc = wn + nt * 8 + (lane & 3) * 2;
            if (r0 < N_NODES)
                *(float2*)&g_h[(size_t)r0 * HF + cc] =
                    make_float2(acc[mt][nt][0], acc[mt][nt][1]);
            if (r0 + 8 < N_NODES)
                *(float2*)&g_h[(size_t)(r0 + 8) * HF + cc] =
                    make_float2(acc[mt][nt][2], acc[mt][nt][3]);
        }
    }
}

// ---------------- generic guarded SGEMM (small GEMMs) -----------------------
template<int BM,int BN,int BK,int TM,int TN,int RELU,int BIAS>
__global__ void sgemm_kernel(const float* __restrict__ A,
                             const float* __restrict__ B,
                             const float* __restrict__ bias,
                             float* __restrict__ C,
                             int M, int N, int K)
{
    __shared__ float As[BK][BM+4];
    __shared__ float Bs[BK][BN+4];
    const int t  = threadIdx.x;                 // 256 threads
    const int m0 = blockIdx.y*BM, n0 = blockIdx.x*BN;
    const int tx = t % (BN/TN), ty = t / (BN/TN);

    float acc[TM][TN];
    #pragma unroll
    for (int i=0;i<TM;i++)
        #pragma unroll
        for (int j=0;j<TN;j++) acc[i][j]=0.f;

    for (int k0=0;k0<K;k0+=BK) {
        #pragma unroll
        for (int i=0;i<(BM*BK)/256;i++){
            int lin = t + 256*i;
            int r = lin / BK, c = lin % BK;
            float v=0.f;
            if (m0+r<M && k0+c<K) v = A[(size_t)(m0+r)*K + k0+c];
            As[c][r]=v;
        }
        #pragma unroll
        for (int i=0;i<(BN*BK)/256;i++){
            int lin = t + 256*i;
            int r = lin / BN, c = lin % BN;
            float v=0.f;
            if (k0+r<K && n0+c<N) v = B[(size_t)(k0+r)*N + n0+c];
            Bs[r][c]=v;
        }
        __syncthreads();
        #pragma unroll
        for (int k=0;k<BK;k++){
            float ra[TM], rb[TN];
            #pragma unroll
            for (int i=0;i<TM;i++) ra[i]=As[k][ty*TM+i];
            #pragma unroll
            for (int j=0;j<TN;j++) rb[j]=Bs[k][tx*TN+j];
            #pragma unroll
            for (int i=0;i<TM;i++)
                #pragma unroll
                for (int j=0;j<TN;j++) acc[i][j] += ra[i]*rb[j];
        }
        __syncthreads();
    }
    #pragma unroll
    for (int i=0;i<TM;i++){
        int m = m0+ty*TM+i;
        if (m>=M) continue;
        #pragma unroll
        for (int j=0;j<TN;j++){
            int n = n0+tx*TN+j;
            if (n>=N) continue;
            float v = acc[i][j];
            if (BIAS) v += bias[n];
            if (RELU) v = fmaxf(v,0.f);
            C[(size_t)m*N+n] = v;
        }
    }
}

// ---------------- per-node attention logits a_s, a_d ------------------------
__global__ void att_kernel(const float* __restrict__ att_src,
                           const float* __restrict__ att_dst)
{
    int warp = (blockIdx.x*blockDim.x + threadIdx.x) >> 5;
    int lane = threadIdx.x & 31;
    if (warp >= N_NODES) return;
    const float* hr = g_h + (size_t)warp*HF;
    #pragma unroll
    for (int h=0;h<NH;h++){
        float hv = hr[h*FH+lane];
        float vs = hv*att_src[h*FH+lane];
        float vd = hv*att_dst[h*FH+lane];
        #pragma unroll
        for (int s=16;s>0;s>>=1){
            vs += __shfl_down_sync(0xffffffffu,vs,s);
            vd += __shfl_down_sync(0xffffffffu,vd,s);
        }
        if (lane==0){ g_as[warp*NH+h]=vs; g_ad[warp*NH+h]=vd; }
    }
}

// ---------------- CSR build --------------------------------------------------
__global__ void zero_deg_kernel(){
    int i = blockIdx.x*blockDim.x+threadIdx.x;
    if (i<N_NODES) g_deg[i]=0;
}
__global__ void count_kernel(const int* __restrict__ ei){
    int e = blockIdx.x*blockDim.x+threadIdx.x;
    if (e<N_EDGES) atomicAdd(&g_deg[ei[N_EDGES+e]],1);
}
__global__ void scan_kernel(){
    __shared__ int sm[1024];
    int t = threadIdx.x;
    const int CH = (N_NODES + 1023)/1024;   // 30
    int base = t*CH;
    int s=0;
    for (int i=0;i<CH;i++){ int idx=base+i; if(idx<N_NODES) s+=g_deg[idx]; }
    sm[t]=s; __syncthreads();
    for (int st=1; st<1024; st<<=1){
        int v = (t>=st)? sm[t-st]:0;
        __syncthreads();
        sm[t]+=v;
        __syncthreads();
    }
    int run = sm[t]-s;                      // exclusive prefix
    for (int i=0;i<CH;i++){
        int idx=base+i;
        if (idx<N_NODES){ g_off[idx]=run; g_cur[idx]=run; run+=g_deg[idx]; }
    }
    if (t==1023) g_off[N_NODES]=sm[1023];
}
__global__ void scatter_kernel(const int* __restrict__ ei){
    int e = blockIdx.x*blockDim.x+threadIdx.x;
    if (e<N_EDGES){
        int d = ei[N_EDGES+e];
        int p = atomicAdd(&g_cur[d],1);
        g_srcs[p] = ei[e];
    }
}

// ---------------- fused softmax + aggregate per dst node --------------------
__global__ void agg_kernel(const float* __restrict__ bias_gat)
{
    const int node = blockIdx.x;
    const int t    = threadIdx.x;
    const int head = t >> 5;

    __shared__ int   s_src[64];
    __shared__ float s_p[64][NH];
    __shared__ float s_m[NH];
    __shared__ float s_ps[NH];
    __shared__ float s_den[NH];
    __shared__ float wmax[8][NH];
    __shared__ float red[256];

    const int off = g_off[node];
    const int deg = g_off[node+1]-off;

    float adv[NH];
    #pragma unroll
    for (int h=0;h<NH;h++) adv[h]=g_ad[node*NH+h];

    float lm[NH];
    #pragma unroll
    for (int h=0;h<NH;h++){
        float l = g_as[node*NH+h] + adv[h];
        lm[h] = (l>0.f) ? l : NEG*l;
    }
    for (int e=t; e<deg; e+=256){
        int s = g_srcs[off+e];
        #pragma unroll
        for (int h=0;h<NH;h++){
            float l = g_as[s*NH+h] + adv[h];
            l = (l>0.f) ? l : NEG*l;
            lm[h] = fmaxf(lm[h], l);
        }
    }
    #pragma unroll
    for (int h=0;h<NH;h++){
        float v = lm[h];
        #pragma unroll
        for (int st=16;st>0;st>>=1) v = fmaxf(v, __shfl_xor_sync(0xffffffffu,v,st));
        lm[h]=v;
    }
    if ((t&31)==0){
        #pragma unroll
        for (int h=0;h<NH;h++) wmax[t>>5][h]=lm[h];
    }
    __syncthreads();
    if (t<NH){
        float m = wmax[0][t];
        #pragma unroll
        for (int w=1;w<8;w++) m = fmaxf(m, wmax[w][t]);
        s_m[t]=m;
        float l = g_as[node*NH+t] + g_ad[node*NH+t];
        l = (l>0.f) ? l : NEG*l;
        float p = expf(l-m);
        s_ps[t]=p; s_den[t]=p;
    }
    __syncthreads();

    float acc  = g_h[(size_t)node*HF + t] * s_ps[head];   // self loop message
    float dloc = 0.f;
    for (int c0=0; c0<deg; c0+=64){
        int nc = min(64, deg-c0);
        if (t<nc) s_src[t] = g_srcs[off+c0+t];
        __syncthreads();
        for (int pr=t; pr<nc*NH; pr+=256){
            int e = pr>>3, h = pr&7;
            int s = s_src[e];
            float l = g_as[s*NH+h] + adv[h];
            l = (l>0.f) ? l : NEG*l;
            float p = expf(l - s_m[h]);
            s_p[e][h]=p;
            dloc += p;
        }
        __syncthreads();
        #pragma unroll 4
        for (int e=0;e<nc;e++){
            acc += g_h[(size_t)s_src[e]*HF + t] * s_p[e][head];
        }
        __syncthreads();
    }

    red[t]=dloc; __syncthreads();
    if (t<NH){
        float d = s_den[t];
        #pragma unroll
        for (int j=0;j<32;j++) d += red[t+8*j];
        s_den[t]=d;
    }
    __syncthreads();

    float v = acc / s_den[head] + bias_gat[t];
    g_gat[(size_t)node*HF + t] = fmaxf(v, 0.f);
}

// ---------------- launch -----------------------------------------------------
extern "C" void kernel_launch(void* const* d_in, const int* in_sizes, int n_in,
                              void* d_out, int out_size)
{
    const float* x        = (const float*)d_in[0];
    const int*   ei       = (const int*)  d_in[1];
    const float* W        = (const float*)d_in[3];
    const float* att_src  = (const float*)d_in[4];
    const float* att_dst  = (const float*)d_in[5];
    const float* bias_gat = (const float*)d_in[6];
    const float* emb_W    = (const float*)d_in[7];
    const float* emb_b    = (const float*)d_in[8];
    const float* dec_W1   = (const float*)d_in[9];
    const float* dec_b1   = (const float*)d_in[10];
    const float* dec_W2   = (const float*)d_in[11];
    const float* dec_b2   = (const float*)d_in[12];

    float* recon = (float*)d_out;                              // [N, DIN]
    float* z     = (float*)d_out + (size_t)N_NODES*DIN;        // [N, DEMB]

    float *gatp, *dp;
    cudaGetSymbolAddress((void**)&gatp, g_gat);
    cudaGetSymbolAddress((void**)&dp,   g_d);

    cudaFuncSetAttribute(gemm1_mma_kernel,
                         cudaFuncAttributeMaxDynamicSharedMemorySize, GSMT);

    const int MB = (N_NODES + 127)/128;   // 235

    // 0) bf16 3-split operand prep
    split_x_kernel<<<(int)(((size_t)N_PAD*KSEC + 255)/256), 256>>>(x);
    build_wB_kernel<<<(HF*KTOT + 255)/256, 256>>>(W);
    // 1) h = x @ W via mma.sync bf16x3   [30000,1000] x [1000,256]
    gemm1_mma_kernel<<<MB, 256, GSMT>>>();
    // 2) a_s, a_d
    att_kernel<<<(N_NODES*32+255)/256,256>>>(att_src, att_dst);
    // 3) CSR by dst
    zero_deg_kernel<<<(N_NODES+255)/256,256>>>();
    count_kernel  <<<(N_EDGES+255)/256,256>>>(ei);
    scan_kernel   <<<1,1024>>>();
    scatter_kernel<<<(N_EDGES+255)/256,256>>>(ei);
    // 4) attention softmax + aggregate + bias + relu
    agg_kernel<<<N_NODES,256>>>(bias_gat);
    // 5) z = gat @ emb_W + emb_b       [30000,256] x [256,64]
    sgemm_kernel<128,64,32,8,4,0,1><<<dim3(1,MB),256>>>(gatp, emb_W, emb_b, z,
                                                        N_NODES, DEMB, HF);
    // 6) d = relu(z @ dec_W1 + dec_b1) [30000,64] x [64,32]
    sgemm_kernel<128,64,32,8,4,1,1><<<dim3(1,MB),256>>>(z, dec_W1, dec_b1, dp,
                                                        N_NODES, FH, DEMB);
    // 7) recon = d @ dec_W2 + dec_b2   [30000,32] x [32,1000]
    sgemm_kernel<128,64,32,8,4,0,1><<<dim3((DIN+63)/64,MB),256>>>(dp, dec_W2, dec_b2,
                                                                  recon,
                                                                  N_NODES, DIN, FH);
}

// round 6
// speedup vs baseline: 1.0560x; 1.0560x over previous
#include <cuda_runtime.h>
#include <cuda_bf16.h>
#include <cstdint>

#define N_NODES 30000
#define N_PAD   30080      // 235 * 128
#define N_EDGES 480000
#define DIN     1000
#define KSEC    1024       // padded section K
#define KTOT    3072       // 3 sections
#define NH      8
#define FH      32
#define HF      256        // NH*FH
#define DEMB    64
#define NEG     0.2f

// ---------------- scratch (device globals; no allocation allowed) ----------
__device__ __nv_bfloat16 g_xhi[(size_t)N_PAD*KSEC];
__device__ __nv_bfloat16 g_xlo[(size_t)N_PAD*KSEC];
__device__ __nv_bfloat16 g_wB [(size_t)HF*KTOT];    // B' [N=256][K=3072] K-major
__device__ float g_h   [(size_t)N_NODES*HF];   // x@W
__device__ float g_as  [N_NODES*NH];
__device__ float g_ad  [N_NODES*NH];
__device__ int   g_deg [N_NODES];
__device__ int   g_off [N_NODES+1];
__device__ int   g_cur [N_NODES];
__device__ int   g_srcs[N_EDGES];              // src ids sorted by dst
__device__ float g_gat [(size_t)N_NODES*HF];   // relu(GAT out + bias)
__device__ float g_d   [(size_t)N_NODES*FH];   // decoder hidden

// ======================= helpers ============================================
__device__ __forceinline__ uint32_t smem_to_u32(const void* p) {
    uint32_t a;
    asm("{ .reg .u64 t; cvta.to.shared.u64 t, %1; cvt.u32.u64 %0, t; }"
        : "=r"(a) : "l"(p));
    return a;
}
__device__ __forceinline__ void cpasync16(uint32_t saddr, const void* gp) {
    asm volatile("cp.async.cg.shared.global [%0], [%1], 16;" :: "r"(saddr), "l"(gp));
}
__device__ __forceinline__ void ldm_x4(uint32_t& r0, uint32_t& r1,
                                       uint32_t& r2, uint32_t& r3, uint32_t a) {
    asm volatile("ldmatrix.sync.aligned.m8n8.x4.shared.b16 {%0,%1,%2,%3}, [%4];"
                 : "=r"(r0), "=r"(r1), "=r"(r2), "=r"(r3) : "r"(a));
}
__device__ __forceinline__ void mma_bf16(float* c, const uint32_t* a,
                                         uint32_t b0, uint32_t b1) {
    asm volatile(
        "mma.sync.aligned.m16n8k16.row.col.f32.bf16.bf16.f32 "
        "{%0,%1,%2,%3}, {%4,%5,%6,%7}, {%8,%9}, {%0,%1,%2,%3};"
        : "+f"(c[0]), "+f"(c[1]), "+f"(c[2]), "+f"(c[3])
        : "r"(a[0]), "r"(a[1]), "r"(a[2]), "r"(a[3]), "r"(b0), "r"(b1));
}

// ======================= split / pack kernels ===============================
__global__ void split_x_kernel(const float* __restrict__ x) {
    size_t idx = (size_t)blockIdx.x * blockDim.x + threadIdx.x;
    if (idx >= (size_t)N_PAD * KSEC) return;
    int r = (int)(idx >> 10);
    int c = (int)(idx & 1023);
    float v = (r < N_NODES && c < DIN) ? x[(size_t)r * DIN + c] : 0.f;
    __nv_bfloat16 hi = __float2bfloat16(v);
    g_xhi[idx] = hi;
    g_xlo[idx] = __float2bfloat16(v - __bfloat162float(hi));
}
__global__ void build_wB_kernel(const float* __restrict__ W) {
    int idx = blockIdx.x * blockDim.x + threadIdx.x;       // over 256*3072
    if (idx >= HF * KTOT) return;
    int n  = idx / KTOT;
    int kk = idx % KTOT;
    int s  = kk >> 10;
    int k  = kk & 1023;
    float v = (k < DIN) ? W[(size_t)k * HF + n] : 0.f;
    __nv_bfloat16 hi = __float2bfloat16(v);
    g_wB[idx] = (s == 2) ? __float2bfloat16(v - __bfloat162float(hi)) : hi;
}

// ======================= bf16 mma.sync GEMM1 (+fused att) ===================
// C[30080,256] = A'[30080,3072]bf16 @ B'[3072,256]bf16 (B stored [256][3072])
// BM=128 BN=128 BK=32, 256 threads, 8 warps (4 m x 2 n), warp tile 32x64.
// Epilogue also computes a_s[n,h], a_d[n,h] (each warp tile spans 2 full heads).
#define BKC  32
#define LDSM 40           // BKC + 8 pad elements (80B row stride)
#define NCH  96           // 3072/32

__global__ void __launch_bounds__(256) gemm1_mma_kernel(
    const float* __restrict__ att_src, const float* __restrict__ att_dst)
{
    __shared__ __nv_bfloat16 sA[2][128][LDSM];
    __shared__ __nv_bfloat16 sB[2][128][LDSM];
    const int t    = threadIdx.x;
    const int lane = t & 31;
    const int wid  = t >> 5;
    const int wm   = (wid & 3) * 32;
    const int wn   = (wid >> 2) * 64;
    const int m0   = blockIdx.y * 128;
    const int n0   = blockIdx.x * 128;

    float acc[2][8][4];
    #pragma unroll
    for (int i = 0; i < 2; i++)
        #pragma unroll
        for (int j = 0; j < 8; j++)
            #pragma unroll
            for (int q = 0; q < 4; q++) acc[i][j][q] = 0.f;

    // A-frag ldmatrix row/col (within warp tile)
    const int a_r = (lane & 7) + ((lane >> 3) & 1) * 8;
    const int a_c = (lane >> 4) * 8;
    // B-frag ldmatrix row/col
    const int b_r = ((lane >> 4) & 1) * 8 + (lane & 7);
    const int b_c = ((lane >> 3) & 1) * 8;

    // Each stage tile: 128 rows x 32 cols bf16 = 512 x 16B chunks per operand.
    auto load_stage = [&](int s, int c) {
        const int kp  = c * BKC;
        const int sec = kp >> 10;
        const int ko  = kp & 1023;
        const __nv_bfloat16* Abase = ((sec == 1) ? g_xlo : g_xhi)
                                     + (size_t)m0 * KSEC + ko;
        const __nv_bfloat16* Bbase = g_wB + (size_t)n0 * KTOT + kp;
        #pragma unroll
        for (int i = 0; i < 2; i++) {
            int u  = t + 256 * i;
            int r  = u >> 2;            // 0..127
            int ch = (u & 3) * 8;       // element offset 0,8,16,24
            cpasync16(smem_to_u32(&sA[s][r][ch]), Abase + (size_t)r * KSEC + ch);
            cpasync16(smem_to_u32(&sB[s][r][ch]), Bbase + (size_t)r * KTOT + ch);
        }
    };

    load_stage(0, 0);
    asm volatile("cp.async.commit_group;" ::: "memory");
    load_stage(1, 1);
    asm volatile("cp.async.commit_group;" ::: "memory");

    for (int c = 0; c < NCH; c++) {
        const int s = c & 1;
        asm volatile("cp.async.wait_group 1;" ::: "memory");
        __syncthreads();

        #pragma unroll
        for (int ks = 0; ks < 2; ks++) {
            const int kb = ks * 16;
            uint32_t a[2][4];
            #pragma unroll
            for (int mt = 0; mt < 2; mt++) {
                uint32_t ad = smem_to_u32(&sA[s][wm + mt * 16 + a_r][kb + a_c]);
                ldm_x4(a[mt][0], a[mt][1], a[mt][2], a[mt][3], ad);
            }
            #pragma unroll
            for (int nt4 = 0; nt4 < 4; nt4++) {
                uint32_t b0, b1, b2, b3;
                uint32_t bd = smem_to_u32(&sB[s][wn + nt4 * 16 + b_r][kb + b_c]);
                ldm_x4(b0, b1, b2, b3, bd);
                #pragma unroll
                for (int mt = 0; mt < 2; mt++) {
                    mma_bf16(acc[mt][nt4 * 2 + 0], a[mt], b0, b1);
                    mma_bf16(acc[mt][nt4 * 2 + 1], a[mt], b2, b3);
                }
            }
        }
        __syncthreads();
        if (c + 2 < NCH) load_stage(s, c + 2);
        asm volatile("cp.async.commit_group;" ::: "memory");
    }

    // ---- epilogue 1: write C fragments to g_h ----
    #pragma unroll
    for (int mt = 0; mt < 2; mt++) {
        const int r0 = m0 + wm + mt * 16 + (lane >> 2);
        #pragma unroll
        for (int nt = 0; nt < 8; nt++) {
            const int cc = n0 + wn + nt * 8 + (lane & 3) * 2;
            if (r0 < N_NODES)
                *(float2*)&g_h[(size_t)r0 * HF + cc] =
                    make_float2(acc[mt][nt][0], acc[mt][nt][1]);
            if (r0 + 8 < N_NODES)
                *(float2*)&g_h[(size_t)(r0 + 8) * HF + cc] =
                    make_float2(acc[mt][nt][2], acc[mt][nt][3]);
        }
    }

    // ---- epilogue 2: fused a_s / a_d (warp tile spans 2 complete heads) ----
    {
        const int head0 = (n0 + wn) >> 5;   // first head covered by this warp
        float2 sv[8], dv[8];
        #pragma unroll
        for (int nt = 0; nt < 8; nt++) {
            const int cc = n0 + wn + nt * 8 + (lane & 3) * 2;
            sv[nt] = *(const float2*)&att_src[cc];
            dv[nt] = *(const float2*)&att_dst[cc];
        }
        #pragma unroll
        for (int mt = 0; mt < 2; mt++) {
            #pragma unroll
            for (int hf = 0; hf < 2; hf++) {     // two heads in this tile
                float vs0 = 0.f, vd0 = 0.f, vs1 = 0.f, vd1 = 0.f;
                #pragma unroll
                for (int j = 0; j < 4; j++) {
                    const int nt = hf * 4 + j;
                    vs0 += acc[mt][nt][0] * sv[nt].x + acc[mt][nt][1] * sv[nt].y;
                    vd0 += acc[mt][nt][0] * dv[nt].x + acc[mt][nt][1] * dv[nt].y;
                    vs1 += acc[mt][nt][2] * sv[nt].x + acc[mt][nt][3] * sv[nt].y;
                    vd1 += acc[mt][nt][2] * dv[nt].x + acc[mt][nt][3] * dv[nt].y;
                }
                // quad reduction over (lane&3): covers all 8 cols per n-group
                vs0 += __shfl_xor_sync(0xffffffffu, vs0, 1);
                vs0 += __shfl_xor_sync(0xffffffffu, vs0, 2);
                vd0 += __shfl_xor_sync(0xffffffffu, vd0, 1);
                vd0 += __shfl_xor_sync(0xffffffffu, vd0, 2);
                vs1 += __shfl_xor_sync(0xffffffffu, vs1, 1);
                vs1 += __shfl_xor_sync(0xffffffffu, vs1, 2);
                vd1 += __shfl_xor_sync(0xffffffffu, vd1, 1);
                vd1 += __shfl_xor_sync(0xffffffffu, vd1, 2);
                if ((lane & 3) == 0) {
                    const int r0 = m0 + wm + mt * 16 + (lane >> 2);
                    const int h  = head0 + hf;
                    if (r0 < N_NODES)     { g_as[r0*NH + h] = vs0; g_ad[r0*NH + h] = vd0; }
                    if (r0 + 8 < N_NODES) { g_as[(r0+8)*NH + h] = vs1; g_ad[(r0+8)*NH + h] = vd1; }
                }
            }
        }
    }
}

// ---------------- generic guarded SGEMM (small GEMMs) -----------------------
template<int BM,int BN,int BK,int TM,int TN,int RELU,int BIAS>
__global__ void sgemm_kernel(const float* __restrict__ A,
                             const float* __restrict__ B,
                             const float* __restrict__ bias,
                             float* __restrict__ C,
                             int M, int N, int K)
{
    __shared__ float As[BK][BM+4];
    __shared__ float Bs[BK][BN+4];
    const int t  = threadIdx.x;                 // 256 threads
    const int m0 = blockIdx.y*BM, n0 = blockIdx.x*BN;
    const int tx = t % (BN/TN), ty = t / (BN/TN);

    float acc[TM][TN];
    #pragma unroll
    for (int i=0;i<TM;i++)
        #pragma unroll
        for (int j=0;j<TN;j++) acc[i][j]=0.f;

    for (int k0=0;k0<K;k0+=BK) {
        #pragma unroll
        for (int i=0;i<(BM*BK)/256;i++){
            int lin = t + 256*i;
            int r = lin / BK, c = lin % BK;
            float v=0.f;
            if (m0+r<M && k0+c<K) v = A[(size_t)(m0+r)*K + k0+c];
            As[c][r]=v;
        }
        #pragma unroll
        for (int i=0;i<(BN*BK)/256;i++){
            int lin = t + 256*i;
            int r = lin / BN, c = lin % BN;
            float v=0.f;
            if (k0+r<K && n0+c<N) v = B[(size_t)(k0+r)*N + n0+c];
            Bs[r][c]=v;
        }
        __syncthreads();
        #pragma unroll
        for (int k=0;k<BK;k++){
            float ra[TM], rb[TN];
            #pragma unroll
            for (int i=0;i<TM;i++) ra[i]=As[k][ty*TM+i];
            #pragma unroll
            for (int j=0;j<TN;j++) rb[j]=Bs[k][tx*TN+j];
            #pragma unroll
            for (int i=0;i<TM;i++)
                #pragma unroll
                for (int j=0;j<TN;j++) acc[i][j] += ra[i]*rb[j];
        }
        __syncthreads();
    }
    #pragma unroll
    for (int i=0;i<TM;i++){
        int m = m0+ty*TM+i;
        if (m>=M) continue;
        #pragma unroll
        for (int j=0;j<TN;j++){
            int n = n0+tx*TN+j;
            if (n>=N) continue;
            float v = acc[i][j];
            if (BIAS) v += bias[n];
            if (RELU) v = fmaxf(v,0.f);
            C[(size_t)m*N+n] = v;
        }
    }
}

// ---------------- CSR build --------------------------------------------------
__global__ void zero_deg_kernel(){
    int i = blockIdx.x*blockDim.x+threadIdx.x;
    if (i<N_NODES) g_deg[i]=0;
}
__global__ void count_kernel(const int* __restrict__ ei){
    int e = blockIdx.x*blockDim.x+threadIdx.x;
    if (e<N_EDGES) atomicAdd(&g_deg[ei[N_EDGES+e]],1);
}
__global__ void scan_kernel(){
    __shared__ int sm[1024];
    int t = threadIdx.x;
    const int CH = (N_NODES + 1023)/1024;   // 30
    int base = t*CH;
    int s=0;
    for (int i=0;i<CH;i++){ int idx=base+i; if(idx<N_NODES) s+=g_deg[idx]; }
    sm[t]=s; __syncthreads();
    for (int st=1; st<1024; st<<=1){
        int v = (t>=st)? sm[t-st]:0;
        __syncthreads();
        sm[t]+=v;
        __syncthreads();
    }
    int run = sm[t]-s;                      // exclusive prefix
    for (int i=0;i<CH;i++){
        int idx=base+i;
        if (idx<N_NODES){ g_off[idx]=run; g_cur[idx]=run; run+=g_deg[idx]; }
    }
    if (t==1023) g_off[N_NODES]=sm[1023];
}
__global__ void scatter_kernel(const int* __restrict__ ei){
    int e = blockIdx.x*blockDim.x+threadIdx.x;
    if (e<N_EDGES){
        int d = ei[N_EDGES+e];
        int p = atomicAdd(&g_cur[d],1);
        g_srcs[p] = ei[e];
    }
}

// ---------------- fused softmax + aggregate per dst node --------------------
__global__ void agg_kernel(const float* __restrict__ bias_gat)
{
    const int node = blockIdx.x;
    const int t    = threadIdx.x;
    const int head = t >> 5;

    __shared__ int   s_src[64];
    __shared__ float s_p[64][NH];
    __shared__ float s_m[NH];
    __shared__ float s_ps[NH];
    __shared__ float s_den[NH];
    __shared__ float wmax[8][NH];
    __shared__ float red[256];

    const int off = g_off[node];
    const int deg = g_off[node+1]-off;

    float adv[NH];
    #pragma unroll
    for (int h=0;h<NH;h++) adv[h]=g_ad[node*NH+h];

    float lm[NH];
    #pragma unroll
    for (int h=0;h<NH;h++){
        float l = g_as[node*NH+h] + adv[h];
        lm[h] = (l>0.f) ? l : NEG*l;
    }
    for (int e=t; e<deg; e+=256){
        int s = g_srcs[off+e];
        #pragma unroll
        for (int h=0;h<NH;h++){
            float l = g_as[s*NH+h] + adv[h];
            l = (l>0.f) ? l : NEG*l;
            lm[h] = fmaxf(lm[h], l);
        }
    }
    #pragma unroll
    for (int h=0;h<NH;h++){
        float v = lm[h];
        #pragma unroll
        for (int st=16;st>0;st>>=1) v = fmaxf(v, __shfl_xor_sync(0xffffffffu,v,st));
        lm[h]=v;
    }
    if ((t&31)==0){
        #pragma unroll
        for (int h=0;h<NH;h++) wmax[t>>5][h]=lm[h];
    }
    __syncthreads();
    if (t<NH){
        float m = wmax[0][t];
        #pragma unroll
        for (int w=1;w<8;w++) m = fmaxf(m, wmax[w][t]);
        s_m[t]=m;
        float l = g_as[node*NH+t] + g_ad[node*NH+t];
        l = (l>0.f) ? l : NEG*l;
        float p = expf(l-m);
        s_ps[t]=p; s_den[t]=p;
    }
    __syncthreads();

    float acc  = g_h[(size_t)node*HF + t] * s_ps[head];   // self loop message
    float dloc = 0.f;
    for (int c0=0; c0<deg; c0+=64){
        int nc = min(64, deg-c0);
        if (t<nc) s_src[t] = g_srcs[off+c0+t];
        __syncthreads();
        for (int pr=t; pr<nc*NH; pr+=256){
            int e = pr>>3, h = pr&7;
            int s = s_src[e];
            float l = g_as[s*NH+h] + adv[h];
            l = (l>0.f) ? l : NEG*l;
            float p = expf(l - s_m[h]);
            s_p[e][h]=p;
            dloc += p;
        }
        __syncthreads();
        #pragma unroll 4
        for (int e=0;e<nc;e++){
            acc += g_h[(size_t)s_src[e]*HF + t] * s_p[e][head];
        }
        __syncthreads();
    }

    red[t]=dloc; __syncthreads();
    if (t<NH){
        float d = s_den[t];
        #pragma unroll
        for (int j=0;j<32;j++) d += red[t+8*j];
        s_den[t]=d;
    }
    __syncthreads();

    float v = acc / s_den[head] + bias_gat[t];
    g_gat[(size_t)node*HF + t] = fmaxf(v, 0.f);
}

// ---------------- launch -----------------------------------------------------
extern "C" void kernel_launch(void* const* d_in, const int* in_sizes, int n_in,
                              void* d_out, int out_size)
{
    const float* x        = (const float*)d_in[0];
    const int*   ei       = (const int*)  d_in[1];
    const float* W        = (const float*)d_in[3];
    const float* att_src  = (const float*)d_in[4];
    const float* att_dst  = (const float*)d_in[5];
    const float* bias_gat = (const float*)d_in[6];
    const float* emb_W    = (const float*)d_in[7];
    const float* emb_b    = (const float*)d_in[8];
    const float* dec_W1   = (const float*)d_in[9];
    const float* dec_b1   = (const float*)d_in[10];
    const float* dec_W2   = (const float*)d_in[11];
    const float* dec_b2   = (const float*)d_in[12];

    float* recon = (float*)d_out;                              // [N, DIN]
    float* z     = (float*)d_out + (size_t)N_NODES*DIN;        // [N, DEMB]

    float *gatp, *dp;
    cudaGetSymbolAddress((void**)&gatp, g_gat);
    cudaGetSymbolAddress((void**)&dp,   g_d);

    const int MB = (N_NODES + 127)/128;   // 235

    // 0) bf16 3-split operand prep
    split_x_kernel<<<(int)(((size_t)N_PAD*KSEC + 255)/256), 256>>>(x);
    build_wB_kernel<<<(HF*KTOT + 255)/256, 256>>>(W);
    // 1) h = x @ W via mma.sync bf16x3 (+ fused a_s/a_d)
    gemm1_mma_kernel<<<dim3(2, MB), 256>>>(att_src, att_dst);
    // 2) CSR by dst
    zero_deg_kernel<<<(N_NODES+255)/256,256>>>();
    count_kernel  <<<(N_EDGES+255)/256,256>>>(ei);
    scan_kernel   <<<1,1024>>>();
    scatter_kernel<<<(N_EDGES+255)/256,256>>>(ei);
    // 3) attention softmax + aggregate + bias + relu
    agg_kernel<<<N_NODES,256>>>(bias_gat);
    // 4) z = gat @ emb_W + emb_b       [30000,256] x [256,64]
    sgemm_kernel<128,64,32,8,4,0,1><<<dim3(1,MB),256>>>(gatp, emb_W, emb_b, z,
                                                        N_NODES, DEMB, HF);
    // 5) d = relu(z @ dec_W1 + dec_b1) [30000,64] x [64,32]
    sgemm_kernel<128,64,32,8,4,1,1><<<dim3(1,MB),256>>>(z, dec_W1, dec_b1, dp,
                                                        N_NODES, FH, DEMB);
    // 6) recon = d @ dec_W2 + dec_b2   [30000,32] x [32,1000]
    sgemm_kernel<128,64,32,8,4,0,1><<<dim3((DIN+63)/64,MB),256>>>(dp, dec_W2, dec_b2,
                                                                  recon,
                                                                  N_NODES, DIN, FH);
}

// round 7
// speedup vs baseline: 1.2582x; 1.1915x over previous
#include <cuda_runtime.h>
#include <cuda_bf16.h>
#include <cstdint>

#define N_NODES 30000
#define N_PAD   30080      // 235 * 128
#define N_EDGES 480000
#define DIN     1000
#define KSEC    1024       // padded section K
#define KTOT    3072       // 3 sections
#define NH      8
#define FH      32
#define HF      256        // NH*FH
#define DEMB    64
#define NEG     0.2f

// ---------------- scratch (device globals; no allocation allowed) ----------
__device__ __nv_bfloat16 g_xhi[(size_t)N_PAD*KSEC];
__device__ __nv_bfloat16 g_xlo[(size_t)N_PAD*KSEC];
__device__ __nv_bfloat16 g_wB [(size_t)HF*KTOT];    // B' [N=256][K=3072] K-major
__device__ float g_h   [(size_t)N_NODES*HF];   // x@W
__device__ float g_as  [N_NODES*NH];
__device__ float g_ad  [N_NODES*NH];
__device__ int   g_deg [N_NODES];
__device__ int   g_off [N_NODES+1];
__device__ int   g_cur [N_NODES];
__device__ int   g_srcs[N_EDGES];              // src ids sorted by dst
__device__ float g_gat [(size_t)N_NODES*HF];   // relu(GAT out + bias)
__device__ float g_d   [(size_t)N_NODES*FH];   // decoder hidden

// ======================= helpers ============================================
__device__ __forceinline__ uint32_t smem_to_u32(const void* p) {
    uint32_t a;
    asm("{ .reg .u64 t; cvta.to.shared.u64 t, %1; cvt.u32.u64 %0, t; }"
        : "=r"(a) : "l"(p));
    return a;
}
__device__ __forceinline__ void cpasync16(uint32_t saddr, const void* gp) {
    asm volatile("cp.async.cg.shared.global [%0], [%1], 16;" :: "r"(saddr), "l"(gp));
}
__device__ __forceinline__ void ldm_x4(uint32_t& r0, uint32_t& r1,
                                       uint32_t& r2, uint32_t& r3, uint32_t a) {
    asm volatile("ldmatrix.sync.aligned.m8n8.x4.shared.b16 {%0,%1,%2,%3}, [%4];"
                 : "=r"(r0), "=r"(r1), "=r"(r2), "=r"(r3) : "r"(a));
}
__device__ __forceinline__ void mma_bf16(float* c, const uint32_t* a,
                                         uint32_t b0, uint32_t b1) {
    asm volatile(
        "mma.sync.aligned.m16n8k16.row.col.f32.bf16.bf16.f32 "
        "{%0,%1,%2,%3}, {%4,%5,%6,%7}, {%8,%9}, {%0,%1,%2,%3};"
        : "+f"(c[0]), "+f"(c[1]), "+f"(c[2]), "+f"(c[3])
        : "r"(a[0]), "r"(a[1]), "r"(a[2]), "r"(a[3]), "r"(b0), "r"(b1));
}

// ======================= split / pack kernels ===============================
// 8 elements per thread: float4 x2 in, uint4 out to hi and lo.
__global__ void split_x_kernel(const float* __restrict__ x) {
    size_t g8 = ((size_t)blockIdx.x * blockDim.x + threadIdx.x);
    if (g8 >= (size_t)N_PAD * KSEC / 8) return;
    size_t idx = g8 * 8;
    int r  = (int)(idx >> 10);
    int c0 = (int)(idx & 1023);
    float v[8];
    if (r < N_NODES && c0 + 7 < DIN) {
        const float4 f0 = *(const float4*)&x[(size_t)r * DIN + c0];
        const float4 f1 = *(const float4*)&x[(size_t)r * DIN + c0 + 4];
        v[0]=f0.x; v[1]=f0.y; v[2]=f0.z; v[3]=f0.w;
        v[4]=f1.x; v[5]=f1.y; v[6]=f1.z; v[7]=f1.w;
    } else {
        #pragma unroll
        for (int i = 0; i < 8; i++) {
            int c = c0 + i;
            v[i] = (r < N_NODES && c < DIN) ? x[(size_t)r * DIN + c] : 0.f;
        }
    }
    __nv_bfloat16 hi[8], lo[8];
    #pragma unroll
    for (int i = 0; i < 8; i++) {
        hi[i] = __float2bfloat16(v[i]);
        lo[i] = __float2bfloat16(v[i] - __bfloat162float(hi[i]));
    }
    *(uint4*)&g_xhi[idx] = *(const uint4*)hi;
    *(uint4*)&g_xlo[idx] = *(const uint4*)lo;
}
__global__ void build_wB_kernel(const float* __restrict__ W) {
    int idx = blockIdx.x * blockDim.x + threadIdx.x;       // over 256*3072
    if (idx >= HF * KTOT) return;
    int n  = idx / KTOT;
    int kk = idx % KTOT;
    int s  = kk >> 10;
    int k  = kk & 1023;
    float v = (k < DIN) ? W[(size_t)k * HF + n] : 0.f;
    __nv_bfloat16 hi = __float2bfloat16(v);
    g_wB[idx] = (s == 2) ? __float2bfloat16(v - __bfloat162float(hi)) : hi;
}

// ======================= bf16 mma.sync GEMM1 (+fused att) ===================
// C[30080,256] = A'[30080,3072]bf16 @ B'[3072,256]bf16 (B stored [256][3072])
// BM=128 BN=128 BK=32, 256 threads, 8 warps (4 m x 2 n), warp tile 32x64.
// Epilogue also computes a_s[n,h], a_d[n,h] (each warp tile spans 2 full heads).
#define BKC  32
#define LDSM 40           // BKC + 8 pad elements (80B row stride)
#define NCH  96           // 3072/32

__global__ void __launch_bounds__(256) gemm1_mma_kernel(
    const float* __restrict__ att_src, const float* __restrict__ att_dst)
{
    __shared__ __nv_bfloat16 sA[2][128][LDSM];
    __shared__ __nv_bfloat16 sB[2][128][LDSM];
    const int t    = threadIdx.x;
    const int lane = t & 31;
    const int wid  = t >> 5;
    const int wm   = (wid & 3) * 32;
    const int wn   = (wid >> 2) * 64;
    const int m0   = blockIdx.y * 128;
    const int n0   = blockIdx.x * 128;

    float acc[2][8][4];
    #pragma unroll
    for (int i = 0; i < 2; i++)
        #pragma unroll
        for (int j = 0; j < 8; j++)
            #pragma unroll
            for (int q = 0; q < 4; q++) acc[i][j][q] = 0.f;

    // A-frag ldmatrix row/col (within warp tile)
    const int a_r = (lane & 7) + ((lane >> 3) & 1) * 8;
    const int a_c = (lane >> 4) * 8;
    // B-frag ldmatrix row/col
    const int b_r = ((lane >> 4) & 1) * 8 + (lane & 7);
    const int b_c = ((lane >> 3) & 1) * 8;

    // Each stage tile: 128 rows x 32 cols bf16 = 512 x 16B chunks per operand.
    auto load_stage = [&](int s, int c) {
        const int kp  = c * BKC;
        const int sec = kp >> 10;
        const int ko  = kp & 1023;
        const __nv_bfloat16* Abase = ((sec == 1) ? g_xlo : g_xhi)
                                     + (size_t)m0 * KSEC + ko;
        const __nv_bfloat16* Bbase = g_wB + (size_t)n0 * KTOT + kp;
        #pragma unroll
        for (int i = 0; i < 2; i++) {
            int u  = t + 256 * i;
            int r  = u >> 2;            // 0..127
            int ch = (u & 3) * 8;       // element offset 0,8,16,24
            cpasync16(smem_to_u32(&sA[s][r][ch]), Abase + (size_t)r * KSEC + ch);
            cpasync16(smem_to_u32(&sB[s][r][ch]), Bbase + (size_t)r * KTOT + ch);
        }
    };

    load_stage(0, 0);
    asm volatile("cp.async.commit_group;" ::: "memory");
    load_stage(1, 1);
    asm volatile("cp.async.commit_group;" ::: "memory");

    for (int c = 0; c < NCH; c++) {
        const int s = c & 1;
        asm volatile("cp.async.wait_group 1;" ::: "memory");
        __syncthreads();

        #pragma unroll
        for (int ks = 0; ks < 2; ks++) {
            const int kb = ks * 16;
            uint32_t a[2][4];
            #pragma unroll
            for (int mt = 0; mt < 2; mt++) {
                uint32_t ad = smem_to_u32(&sA[s][wm + mt * 16 + a_r][kb + a_c]);
                ldm_x4(a[mt][0], a[mt][1], a[mt][2], a[mt][3], ad);
            }
            #pragma unroll
            for (int nt4 = 0; nt4 < 4; nt4++) {
                uint32_t b0, b1, b2, b3;
                uint32_t bd = smem_to_u32(&sB[s][wn + nt4 * 16 + b_r][kb + b_c]);
                ldm_x4(b0, b1, b2, b3, bd);
                #pragma unroll
                for (int mt = 0; mt < 2; mt++) {
                    mma_bf16(acc[mt][nt4 * 2 + 0], a[mt], b0, b1);
                    mma_bf16(acc[mt][nt4 * 2 + 1], a[mt], b2, b3);
                }
            }
        }
        __syncthreads();
        if (c + 2 < NCH) load_stage(s, c + 2);
        asm volatile("cp.async.commit_group;" ::: "memory");
    }

    // ---- epilogue 1: write C fragments to g_h ----
    #pragma unroll
    for (int mt = 0; mt < 2; mt++) {
        const int r0 = m0 + wm + mt * 16 + (lane >> 2);
        #pragma unroll
        for (int nt = 0; nt < 8; nt++) {
            const int cc = n0 + wn + nt * 8 + (lane & 3) * 2;
            if (r0 < N_NODES)
                *(float2*)&g_h[(size_t)r0 * HF + cc] =
                    make_float2(acc[mt][nt][0], acc[mt][nt][1]);
            if (r0 + 8 < N_NODES)
                *(float2*)&g_h[(size_t)(r0 + 8) * HF + cc] =
                    make_float2(acc[mt][nt][2], acc[mt][nt][3]);
        }
    }

    // ---- epilogue 2: fused a_s / a_d (warp tile spans 2 complete heads) ----
    {
        const int head0 = (n0 + wn) >> 5;   // first head covered by this warp
        float2 sv[8], dv[8];
        #pragma unroll
        for (int nt = 0; nt < 8; nt++) {
            const int cc = n0 + wn + nt * 8 + (lane & 3) * 2;
            sv[nt] = *(const float2*)&att_src[cc];
            dv[nt] = *(const float2*)&att_dst[cc];
        }
        #pragma unroll
        for (int mt = 0; mt < 2; mt++) {
            #pragma unroll
            for (int hf = 0; hf < 2; hf++) {     // two heads in this tile
                float vs0 = 0.f, vd0 = 0.f, vs1 = 0.f, vd1 = 0.f;
                #pragma unroll
                for (int j = 0; j < 4; j++) {
                    const int nt = hf * 4 + j;
                    vs0 += acc[mt][nt][0] * sv[nt].x + acc[mt][nt][1] * sv[nt].y;
                    vd0 += acc[mt][nt][0] * dv[nt].x + acc[mt][nt][1] * dv[nt].y;
                    vs1 += acc[mt][nt][2] * sv[nt].x + acc[mt][nt][3] * sv[nt].y;
                    vd1 += acc[mt][nt][2] * dv[nt].x + acc[mt][nt][3] * dv[nt].y;
                }
                // quad reduction over (lane&3): covers all 8 cols per n-group
                vs0 += __shfl_xor_sync(0xffffffffu, vs0, 1);
                vs0 += __shfl_xor_sync(0xffffffffu, vs0, 2);
                vd0 += __shfl_xor_sync(0xffffffffu, vd0, 1);
                vd0 += __shfl_xor_sync(0xffffffffu, vd0, 2);
                vs1 += __shfl_xor_sync(0xffffffffu, vs1, 1);
                vs1 += __shfl_xor_sync(0xffffffffu, vs1, 2);
                vd1 += __shfl_xor_sync(0xffffffffu, vd1, 1);
                vd1 += __shfl_xor_sync(0xffffffffu, vd1, 2);
                if ((lane & 3) == 0) {
                    const int r0 = m0 + wm + mt * 16 + (lane >> 2);
                    const int h  = head0 + hf;
                    if (r0 < N_NODES)     { g_as[r0*NH + h] = vs0; g_ad[r0*NH + h] = vd0; }
                    if (r0 + 8 < N_NODES) { g_as[(r0+8)*NH + h] = vs1; g_ad[(r0+8)*NH + h] = vd1; }
                }
            }
        }
    }
}

// ---------------- generic guarded SGEMM (small GEMMs) -----------------------
template<int BM,int BN,int BK,int TM,int TN,int RELU,int BIAS>
__global__ void sgemm_kernel(const float* __restrict__ A,
                             const float* __restrict__ B,
                             const float* __restrict__ bias,
                             float* __restrict__ C,
                             int M, int N, int K)
{
    __shared__ float As[BK][BM+4];
    __shared__ float Bs[BK][BN+4];
    const int t  = threadIdx.x;                 // 256 threads
    const int m0 = blockIdx.y*BM, n0 = blockIdx.x*BN;
    const int tx = t % (BN/TN), ty = t / (BN/TN);

    float acc[TM][TN];
    #pragma unroll
    for (int i=0;i<TM;i++)
        #pragma unroll
        for (int j=0;j<TN;j++) acc[i][j]=0.f;

    for (int k0=0;k0<K;k0+=BK) {
        #pragma unroll
        for (int i=0;i<(BM*BK)/256;i++){
            int lin = t + 256*i;
            int r = lin / BK, c = lin % BK;
            float v=0.f;
            if (m0+r<M && k0+c<K) v = A[(size_t)(m0+r)*K + k0+c];
            As[c][r]=v;
        }
        #pragma unroll
        for (int i=0;i<(BN*BK)/256;i++){
            int lin = t + 256*i;
            int r = lin / BN, c = lin % BN;
            float v=0.f;
            if (k0+r<K && n0+c<N) v = B[(size_t)(k0+r)*N + n0+c];
            Bs[r][c]=v;
        }
        __syncthreads();
        #pragma unroll
        for (int k=0;k<BK;k++){
            float ra[TM], rb[TN];
            #pragma unroll
            for (int i=0;i<TM;i++) ra[i]=As[k][ty*TM+i];
            #pragma unroll
            for (int j=0;j<TN;j++) rb[j]=Bs[k][tx*TN+j];
            #pragma unroll
            for (int i=0;i<TM;i++)
                #pragma unroll
                for (int j=0;j<TN;j++) acc[i][j] += ra[i]*rb[j];
        }
        __syncthreads();
    }
    #pragma unroll
    for (int i=0;i<TM;i++){
        int m = m0+ty*TM+i;
        if (m>=M) continue;
        #pragma unroll
        for (int j=0;j<TN;j++){
            int n = n0+tx*TN+j;
            if (n>=N) continue;
            float v = acc[i][j];
            if (BIAS) v += bias[n];
            if (RELU) v = fmaxf(v,0.f);
            C[(size_t)m*N+n] = v;
        }
    }
}

// ---------------- CSR build --------------------------------------------------
__global__ void zero_deg_kernel(){
    int i = blockIdx.x*blockDim.x+threadIdx.x;
    if (i<N_NODES) g_deg[i]=0;
}
__global__ void count_kernel(const int* __restrict__ ei){
    int e = blockIdx.x*blockDim.x+threadIdx.x;
    if (e<N_EDGES) atomicAdd(&g_deg[ei[N_EDGES+e]],1);
}
__global__ void scan_kernel(){
    __shared__ int sm[1024];
    int t = threadIdx.x;
    const int CH = (N_NODES + 1023)/1024;   // 30
    int base = t*CH;
    int s=0;
    for (int i=0;i<CH;i++){ int idx=base+i; if(idx<N_NODES) s+=g_deg[idx]; }
    sm[t]=s; __syncthreads();
    for (int st=1; st<1024; st<<=1){
        int v = (t>=st)? sm[t-st]:0;
        __syncthreads();
        sm[t]+=v;
        __syncthreads();
    }
    int run = sm[t]-s;                      // exclusive prefix
    for (int i=0;i<CH;i++){
        int idx=base+i;
        if (idx<N_NODES){ g_off[idx]=run; g_cur[idx]=run; run+=g_deg[idx]; }
    }
    if (t==1023) g_off[N_NODES]=sm[1023];
}
__global__ void scatter_kernel(const int* __restrict__ ei){
    int e = blockIdx.x*blockDim.x+threadIdx.x;
    if (e<N_EDGES){
        int d = ei[N_EDGES+e];
        int p = atomicAdd(&g_cur[d],1);
        g_srcs[p] = ei[e];
    }
}

// ---------------- fused softmax + aggregate per dst node --------------------
// No max subtraction: alpha = exp(l)/sum(exp(l)) is identical, logits are O(1).
__global__ void agg_kernel(const float* __restrict__ bias_gat)
{
    const int node = blockIdx.x;
    const int t    = threadIdx.x;
    const int head = t >> 5;

    __shared__ int   s_src[64];
    __shared__ float s_p[64][NH];
    __shared__ float s_ps[NH];
    __shared__ float red[256];
    __shared__ float s_den[NH];

    const int off = g_off[node];
    const int deg = g_off[node+1]-off;

    float adv[NH];
    #pragma unroll
    for (int h=0;h<NH;h++) adv[h]=g_ad[node*NH+h];

    if (t<NH){
        float l = g_as[node*NH+t] + adv[t];
        l = (l>0.f) ? l : NEG*l;
        s_ps[t] = expf(l);           // self-loop weight
    }
    __syncthreads();

    float acc  = g_h[(size_t)node*HF + t] * s_ps[head];   // self loop message
    float dloc = 0.f;
    for (int c0=0; c0<deg; c0+=64){
        int nc = min(64, deg-c0);
        if (t<nc) s_src[t] = g_srcs[off+c0+t];
        __syncthreads();
        for (int pr=t; pr<nc*NH; pr+=256){
            int e = pr>>3, h = pr&7;
            int s = s_src[e];
            float l = g_as[s*NH+h] + adv[h];
            l = (l>0.f) ? l : NEG*l;
            float p = expf(l);
            s_p[e][h]=p;
            dloc += p;               // partial for head (t&7)
        }
        __syncthreads();
        #pragma unroll 4
        for (int e=0;e<nc;e++){
            acc += g_h[(size_t)s_src[e]*HF + t] * s_p[e][head];
        }
        __syncthreads();
    }

    red[t]=dloc; __syncthreads();
    if (t<NH){
        float d = s_ps[t];           // self-loop term in denominator
        #pragma unroll
        for (int j=0;j<32;j++) d += red[t+8*j];
        s_den[t]=d;
    }
    __syncthreads();

    float v = acc / s_den[head] + bias_gat[t];
    g_gat[(size_t)node*HF + t] = fmaxf(v, 0.f);
}

// ---------------- launch -----------------------------------------------------
extern "C" void kernel_launch(void* const* d_in, const int* in_sizes, int n_in,
                              void* d_out, int out_size)
{
    const float* x        = (const float*)d_in[0];
    const int*   ei       = (const int*)  d_in[1];
    const float* W        = (const float*)d_in[3];
    const float* att_src  = (const float*)d_in[4];
    const float* att_dst  = (const float*)d_in[5];
    const float* bias_gat = (const float*)d_in[6];
    const float* emb_W    = (const float*)d_in[7];
    const float* emb_b    = (const float*)d_in[8];
    const float* dec_W1   = (const float*)d_in[9];
    const float* dec_b1   = (const float*)d_in[10];
    const float* dec_W2   = (const float*)d_in[11];
    const float* dec_b2   = (const float*)d_in[12];

    float* recon = (float*)d_out;                              // [N, DIN]
    float* z     = (float*)d_out + (size_t)N_NODES*DIN;        // [N, DEMB]

    float *gatp, *dp;
    cudaGetSymbolAddress((void**)&gatp, g_gat);
    cudaGetSymbolAddress((void**)&dp,   g_d);

    const int MB = (N_NODES + 127)/128;   // 235

    // 0) bf16 3-split operand prep
    split_x_kernel<<<(int)(((size_t)N_PAD*KSEC/8 + 255)/256), 256>>>(x);
    build_wB_kernel<<<(HF*KTOT + 255)/256, 256>>>(W);
    // 1) h = x @ W via mma.sync bf16x3 (+ fused a_s/a_d)
    gemm1_mma_kernel<<<dim3(2, MB), 256>>>(att_src, att_dst);
    // 2) CSR by dst
    zero_deg_kernel<<<(N_NODES+255)/256,256>>>();
    count_kernel  <<<(N_EDGES+255)/256,256>>>(ei);
    scan_kernel   <<<1,1024>>>();
    scatter_kernel<<<(N_EDGES+255)/256,256>>>(ei);
    // 3) attention softmax + aggregate + bias + relu
    agg_kernel<<<N_NODES,256>>>(bias_gat);
    // 4) z = gat @ emb_W + emb_b       [30000,256] x [256,64]
    sgemm_kernel<128,64,32,8,4,0,1><<<dim3(1,MB),256>>>(gatp, emb_W, emb_b, z,
                                                        N_NODES, DEMB, HF);
    // 5) d = relu(z @ dec_W1 + dec_b1) [30000,64] x [64,32]
    sgemm_kernel<128,64,32,8,4,1,1><<<dim3(1,MB),256>>>(z, dec_W1, dec_b1, dp,
                                                        N_NODES, FH, DEMB);
    // 6) recon = d @ dec_W2 + dec_b2   [30000,32] x [32,1000]
    sgemm_kernel<128,64,32,8,4,0,1><<<dim3((DIN+63)/64,MB),256>>>(dp, dec_W2, dec_b2,
                                                                  recon,
                                                                  N_NODES, DIN, FH);
}

// round 8
// speedup vs baseline: 1.3312x; 1.0580x over previous
#include <cuda_runtime.h>
#include <cuda_bf16.h>
#include <cstdint>

#define N_NODES 30000
#define N_PAD   30080      // 235 * 128
#define N_EDGES 480000
#define DIN     1000
#define KSEC    1024       // padded section K
#define KTOT    3072       // 3 sections
#define NH      8
#define FH      32
#define HF      256        // NH*FH
#define DEMB    64
#define NEG     0.2f

// ---------------- scratch (device globals; no allocation allowed) ----------
__device__ __nv_bfloat16 g_xhi[(size_t)N_PAD*KSEC];
__device__ __nv_bfloat16 g_xlo[(size_t)N_PAD*KSEC];
__device__ __nv_bfloat16 g_wB [(size_t)HF*KTOT];    // B' [N=256][K=3072] K-major
__device__ float g_h   [(size_t)N_NODES*HF];   // x@W
__device__ float g_as  [N_NODES*NH];
__device__ float g_ad  [N_NODES*NH];
__device__ int   g_deg [N_NODES];
__device__ int   g_off [N_NODES+1];
__device__ int   g_cur [N_NODES];
__device__ int   g_srcs[N_EDGES];              // src ids sorted by dst
__device__ float g_gat [(size_t)N_NODES*HF];   // relu(GAT out + bias)
__device__ float g_d   [(size_t)N_NODES*FH];   // decoder hidden

// ======================= helpers ============================================
__device__ __forceinline__ uint32_t smem_to_u32(const void* p) {
    uint32_t a;
    asm("{ .reg .u64 t; cvta.to.shared.u64 t, %1; cvt.u32.u64 %0, t; }"
        : "=r"(a) : "l"(p));
    return a;
}
__device__ __forceinline__ void cpasync16(uint32_t saddr, const void* gp) {
    asm volatile("cp.async.cg.shared.global [%0], [%1], 16;" :: "r"(saddr), "l"(gp));
}
__device__ __forceinline__ void ldm_x4(uint32_t& r0, uint32_t& r1,
                                       uint32_t& r2, uint32_t& r3, uint32_t a) {
    asm volatile("ldmatrix.sync.aligned.m8n8.x4.shared.b16 {%0,%1,%2,%3}, [%4];"
                 : "=r"(r0), "=r"(r1), "=r"(r2), "=r"(r3) : "r"(a));
}
__device__ __forceinline__ void mma_bf16(float* c, const uint32_t* a,
                                         uint32_t b0, uint32_t b1) {
    asm volatile(
        "mma.sync.aligned.m16n8k16.row.col.f32.bf16.bf16.f32 "
        "{%0,%1,%2,%3}, {%4,%5,%6,%7}, {%8,%9}, {%0,%1,%2,%3};"
        : "+f"(c[0]), "+f"(c[1]), "+f"(c[2]), "+f"(c[3])
        : "r"(a[0]), "r"(a[1]), "r"(a[2]), "r"(a[3]), "r"(b0), "r"(b1));
}

// ======================= split / pack kernels ===============================
// 8 elements per thread: float4 x2 in, uint4 out to hi and lo.
__global__ void split_x_kernel(const float* __restrict__ x) {
    size_t g8 = ((size_t)blockIdx.x * blockDim.x + threadIdx.x);
    if (g8 >= (size_t)N_PAD * KSEC / 8) return;
    size_t idx = g8 * 8;
    int r  = (int)(idx >> 10);
    int c0 = (int)(idx & 1023);
    float v[8];
    if (r < N_NODES && c0 + 7 < DIN) {
        const float4 f0 = *(const float4*)&x[(size_t)r * DIN + c0];
        const float4 f1 = *(const float4*)&x[(size_t)r * DIN + c0 + 4];
        v[0]=f0.x; v[1]=f0.y; v[2]=f0.z; v[3]=f0.w;
        v[4]=f1.x; v[5]=f1.y; v[6]=f1.z; v[7]=f1.w;
    } else {
        #pragma unroll
        for (int i = 0; i < 8; i++) {
            int c = c0 + i;
            v[i] = (r < N_NODES && c < DIN) ? x[(size_t)r * DIN + c] : 0.f;
        }
    }
    __nv_bfloat16 hi[8], lo[8];
    #pragma unroll
    for (int i = 0; i < 8; i++) {
        hi[i] = __float2bfloat16(v[i]);
        lo[i] = __float2bfloat16(v[i] - __bfloat162float(hi[i]));
    }
    *(uint4*)&g_xhi[idx] = *(const uint4*)hi;
    *(uint4*)&g_xlo[idx] = *(const uint4*)lo;
}
// also zeroes g_deg (free threads, same-stream ordering before count_kernel)
__global__ void build_wB_kernel(const float* __restrict__ W) {
    int idx = blockIdx.x * blockDim.x + threadIdx.x;       // over 256*3072
    if (idx < N_NODES) g_deg[idx] = 0;
    if (idx >= HF * KTOT) return;
    int n  = idx / KTOT;
    int kk = idx % KTOT;
    int s  = kk >> 10;
    int k  = kk & 1023;
    float v = (k < DIN) ? W[(size_t)k * HF + n] : 0.f;
    __nv_bfloat16 hi = __float2bfloat16(v);
    g_wB[idx] = (s == 2) ? __float2bfloat16(v - __bfloat162float(hi)) : hi;
}

// ======================= bf16 mma.sync GEMM1 (+fused att) ===================
// C[30080,256] = A'[30080,3072]bf16 @ B'[3072,256]bf16 (B stored [256][3072])
// BM=128 BN=128 BK=32, 256 threads, 8 warps (4 m x 2 n), warp tile 32x64.
// 3-stage cp.async pipeline, dynamic smem. 2 CTAs/SM.
#define BKC  32
#define LDSM 40           // BKC + 8 pad elements (80B row stride)
#define NCH  96           // 3072/32
#define STGB 20480u       // bytes per stage (A 10240 + B 10240)
#define GSMT (3u*STGB)    // 61440

__global__ void __launch_bounds__(256, 2) gemm1_mma_kernel(
    const float* __restrict__ att_src, const float* __restrict__ att_dst)
{
    extern __shared__ char gsm[];
    const uint32_t sb = smem_to_u32(gsm);
    const int t    = threadIdx.x;
    const int lane = t & 31;
    const int wid  = t >> 5;
    const int wm   = (wid & 3) * 32;
    const int wn   = (wid >> 2) * 64;
    const int m0   = blockIdx.y * 128;
    const int n0   = blockIdx.x * 128;

    float acc[2][8][4];
    #pragma unroll
    for (int i = 0; i < 2; i++)
        #pragma unroll
        for (int j = 0; j < 8; j++)
            #pragma unroll
            for (int q = 0; q < 4; q++) acc[i][j][q] = 0.f;

    // A-frag ldmatrix row/col (within warp tile)
    const int a_r = (lane & 7) + ((lane >> 3) & 1) * 8;
    const int a_c = (lane >> 4) * 8;
    // B-frag ldmatrix row/col
    const int b_r = ((lane >> 4) & 1) * 8 + (lane & 7);
    const int b_c = ((lane >> 3) & 1) * 8;

    auto sAaddr = [&](int s, int r, int c) -> uint32_t {
        return sb + (uint32_t)s * STGB + (uint32_t)r * (LDSM * 2) + (uint32_t)c * 2;
    };
    auto sBaddr = [&](int s, int r, int c) -> uint32_t {
        return sb + (uint32_t)s * STGB + 10240u + (uint32_t)r * (LDSM * 2) + (uint32_t)c * 2;
    };

    // Each stage tile: 128 rows x 32 cols bf16 = 512 x 16B chunks per operand.
    auto load_stage = [&](int s, int c) {
        const int kp  = c * BKC;
        const int sec = kp >> 10;
        const int ko  = kp & 1023;
        const __nv_bfloat16* Abase = ((sec == 1) ? g_xlo : g_xhi)
                                     + (size_t)m0 * KSEC + ko;
        const __nv_bfloat16* Bbase = g_wB + (size_t)n0 * KTOT + kp;
        #pragma unroll
        for (int i = 0; i < 2; i++) {
            int u  = t + 256 * i;
            int r  = u >> 2;            // 0..127
            int ch = (u & 3) * 8;       // element offset 0,8,16,24
            cpasync16(sAaddr(s, r, ch), Abase + (size_t)r * KSEC + ch);
            cpasync16(sBaddr(s, r, ch), Bbase + (size_t)r * KTOT + ch);
        }
    };

    load_stage(0, 0);
    asm volatile("cp.async.commit_group;" ::: "memory");
    load_stage(1, 1);
    asm volatile("cp.async.commit_group;" ::: "memory");
    load_stage(2, 2);
    asm volatile("cp.async.commit_group;" ::: "memory");

    int s = 0;
    for (int c = 0; c < NCH; c++) {
        asm volatile("cp.async.wait_group 2;" ::: "memory");
        __syncthreads();

        #pragma unroll
        for (int ks = 0; ks < 2; ks++) {
            const int kb = ks * 16;
            uint32_t a[2][4];
            #pragma unroll
            for (int mt = 0; mt < 2; mt++)
                ldm_x4(a[mt][0], a[mt][1], a[mt][2], a[mt][3],
                       sAaddr(s, wm + mt * 16 + a_r, kb + a_c));
            #pragma unroll
            for (int nt4 = 0; nt4 < 4; nt4++) {
                uint32_t b0, b1, b2, b3;
                ldm_x4(b0, b1, b2, b3, sBaddr(s, wn + nt4 * 16 + b_r, kb + b_c));
                #pragma unroll
                for (int mt = 0; mt < 2; mt++) {
                    mma_bf16(acc[mt][nt4 * 2 + 0], a[mt], b0, b1);
                    mma_bf16(acc[mt][nt4 * 2 + 1], a[mt], b2, b3);
                }
            }
        }
        __syncthreads();
        if (c + 3 < NCH) load_stage(s, c + 3);
        asm volatile("cp.async.commit_group;" ::: "memory");
        s = (s == 2) ? 0 : s + 1;
    }

    // ---- epilogue 1: write C fragments to g_h ----
    #pragma unroll
    for (int mt = 0; mt < 2; mt++) {
        const int r0 = m0 + wm + mt * 16 + (lane >> 2);
        #pragma unroll
        for (int nt = 0; nt < 8; nt++) {
            const int cc = n0 + wn + nt * 8 + (lane & 3) * 2;
            if (r0 < N_NODES)
                *(float2*)&g_h[(size_t)r0 * HF + cc] =
                    make_float2(acc[mt][nt][0], acc[mt][nt][1]);
            if (r0 + 8 < N_NODES)
                *(float2*)&g_h[(size_t)(r0 + 8) * HF + cc] =
                    make_float2(acc[mt][nt][2], acc[mt][nt][3]);
        }
    }

    // ---- epilogue 2: fused a_s / a_d (warp tile spans 2 complete heads) ----
    {
        const int head0 = (n0 + wn) >> 5;   // first head covered by this warp
        float2 sv[8], dv[8];
        #pragma unroll
        for (int nt = 0; nt < 8; nt++) {
            const int cc = n0 + wn + nt * 8 + (lane & 3) * 2;
            sv[nt] = *(const float2*)&att_src[cc];
            dv[nt] = *(const float2*)&att_dst[cc];
        }
        #pragma unroll
        for (int mt = 0; mt < 2; mt++) {
            #pragma unroll
            for (int hf = 0; hf < 2; hf++) {     // two heads in this tile
                float vs0 = 0.f, vd0 = 0.f, vs1 = 0.f, vd1 = 0.f;
                #pragma unroll
                for (int j = 0; j < 4; j++) {
                    const int nt = hf * 4 + j;
                    vs0 += acc[mt][nt][0] * sv[nt].x + acc[mt][nt][1] * sv[nt].y;
                    vd0 += acc[mt][nt][0] * dv[nt].x + acc[mt][nt][1] * dv[nt].y;
                    vs1 += acc[mt][nt][2] * sv[nt].x + acc[mt][nt][3] * sv[nt].y;
                    vd1 += acc[mt][nt][2] * dv[nt].x + acc[mt][nt][3] * dv[nt].y;
                }
                vs0 += __shfl_xor_sync(0xffffffffu, vs0, 1);
                vs0 += __shfl_xor_sync(0xffffffffu, vs0, 2);
                vd0 += __shfl_xor_sync(0xffffffffu, vd0, 1);
                vd0 += __shfl_xor_sync(0xffffffffu, vd0, 2);
                vs1 += __shfl_xor_sync(0xffffffffu, vs1, 1);
                vs1 += __shfl_xor_sync(0xffffffffu, vs1, 2);
                vd1 += __shfl_xor_sync(0xffffffffu, vd1, 1);
                vd1 += __shfl_xor_sync(0xffffffffu, vd1, 2);
                if ((lane & 3) == 0) {
                    const int r0 = m0 + wm + mt * 16 + (lane >> 2);
                    const int h  = head0 + hf;
                    if (r0 < N_NODES)     { g_as[r0*NH + h] = vs0; g_ad[r0*NH + h] = vd0; }
                    if (r0 + 8 < N_NODES) { g_as[(r0+8)*NH + h] = vs1; g_ad[(r0+8)*NH + h] = vd1; }
                }
            }
        }
    }
}

// ---------------- generic guarded SGEMM (recon) -----------------------------
template<int BM,int BN,int BK,int TM,int TN,int RELU,int BIAS>
__global__ void sgemm_kernel(const float* __restrict__ A,
                             const float* __restrict__ B,
                             const float* __restrict__ bias,
                             float* __restrict__ C,
                             int M, int N, int K)
{
    __shared__ float As[BK][BM+4];
    __shared__ float Bs[BK][BN+4];
    const int t  = threadIdx.x;                 // 256 threads
    const int m0 = blockIdx.y*BM, n0 = blockIdx.x*BN;
    const int tx = t % (BN/TN), ty = t / (BN/TN);

    float acc[TM][TN];
    #pragma unroll
    for (int i=0;i<TM;i++)
        #pragma unroll
        for (int j=0;j<TN;j++) acc[i][j]=0.f;

    for (int k0=0;k0<K;k0+=BK) {
        #pragma unroll
        for (int i=0;i<(BM*BK)/256;i++){
            int lin = t + 256*i;
            int r = lin / BK, c = lin % BK;
            float v=0.f;
            if (m0+r<M && k0+c<K) v = A[(size_t)(m0+r)*K + k0+c];
            As[c][r]=v;
        }
        #pragma unroll
        for (int i=0;i<(BN*BK)/256;i++){
            int lin = t + 256*i;
            int r = lin / BN, c = lin % BN;
            float v=0.f;
            if (k0+r<K && n0+c<N) v = B[(size_t)(k0+r)*N + n0+c];
            Bs[r][c]=v;
        }
        __syncthreads();
        #pragma unroll
        for (int k=0;k<BK;k++){
            float ra[TM], rb[TN];
            #pragma unroll
            for (int i=0;i<TM;i++) ra[i]=As[k][ty*TM+i];
            #pragma unroll
            for (int j=0;j<TN;j++) rb[j]=Bs[k][tx*TN+j];
            #pragma unroll
            for (int i=0;i<TM;i++)
                #pragma unroll
                for (int j=0;j<TN;j++) acc[i][j] += ra[i]*rb[j];
        }
        __syncthreads();
    }
    if (TN == 4 && n0 + BN <= N) {          // full-width tile: float4 stores
        float4 bv = make_float4(0.f,0.f,0.f,0.f);
        if (BIAS) bv = *(const float4*)&bias[n0 + tx*4];
        #pragma unroll
        for (int i=0;i<TM;i++){
            int m = m0+ty*TM+i;
            if (m>=M) continue;
            float4 v = make_float4(acc[i][0]+bv.x, acc[i][1]+bv.y,
                                   acc[i][2]+bv.z, acc[i][3]+bv.w);
            if (RELU){ v.x=fmaxf(v.x,0.f); v.y=fmaxf(v.y,0.f);
                       v.z=fmaxf(v.z,0.f); v.w=fmaxf(v.w,0.f); }
            *(float4*)&C[(size_t)m*N + n0 + tx*4] = v;
        }
    } else {
        #pragma unroll
        for (int i=0;i<TM;i++){
            int m = m0+ty*TM+i;
            if (m>=M) continue;
            #pragma unroll
            for (int j=0;j<TN;j++){
                int n = n0+tx*TN+j;
                if (n>=N) continue;
                float v = acc[i][j];
                if (BIAS) v += bias[n];
                if (RELU) v = fmaxf(v,0.f);
                C[(size_t)m*N+n] = v;
            }
        }
    }
}

// ---------------- fused z + d kernel ----------------------------------------
// z[128,64] = gat @ emb_W + emb_b ; d[128,32] = relu(z @ dec_W1 + dec_b1)
__global__ void __launch_bounds__(256) zd_kernel(
    const float* __restrict__ emb_W, const float* __restrict__ emb_b,
    const float* __restrict__ dec_W1, const float* __restrict__ dec_b1,
    float* __restrict__ z)
{
    __shared__ float sbuf[10432];
    float (*As)[132] = (float(*)[132])sbuf;            // 32 x 132 (phase 1)
    float (*Bs)[68]  = (float(*)[68])(sbuf + 4224);    // 32 x 68  (phase 1)
    float (*zs)[65]  = (float(*)[65])sbuf;             // 128 x 65 (phase 2)
    float (*W1s)[33] = (float(*)[33])(sbuf + 8320);    // 64 x 33  (phase 2)

    const int t  = threadIdx.x;
    const int tx = t & 15, ty = t >> 4;
    const int m0 = blockIdx.x * 128;

    // ---- phase 1: z tile ----
    float acc[8][4];
    #pragma unroll
    for (int i=0;i<8;i++)
        #pragma unroll
        for (int j=0;j<4;j++) acc[i][j]=0.f;

    for (int k0=0;k0<HF;k0+=32) {
        #pragma unroll
        for (int i=0;i<16;i++){
            int lin = t + 256*i;
            int r = lin >> 5, c = lin & 31;
            As[c][r] = (m0+r < N_NODES) ? g_gat[(size_t)(m0+r)*HF + k0+c] : 0.f;
        }
        #pragma unroll
        for (int i=0;i<8;i++){
            int lin = t + 256*i;
            int r = lin >> 6, c = lin & 63;
            Bs[r][c] = emb_W[(size_t)(k0+r)*DEMB + c];
        }
        __syncthreads();
        #pragma unroll
        for (int k=0;k<32;k++){
            float ra[8], rb[4];
            #pragma unroll
            for (int i=0;i<8;i++) ra[i]=As[k][ty*8+i];
            #pragma unroll
            for (int j=0;j<4;j++) rb[j]=Bs[k][tx*4+j];
            #pragma unroll
            for (int i=0;i<8;i++)
                #pragma unroll
                for (int j=0;j<4;j++) acc[i][j] += ra[i]*rb[j];
        }
        __syncthreads();
    }

    // write z (global + smem), load W1
    const float4 bz = *(const float4*)&emb_b[tx*4];
    #pragma unroll
    for (int i=0;i<8;i++){
        int m = m0 + ty*8 + i;
        float4 v = make_float4(acc[i][0]+bz.x, acc[i][1]+bz.y,
                               acc[i][2]+bz.z, acc[i][3]+bz.w);
        zs[ty*8+i][tx*4+0]=v.x; zs[ty*8+i][tx*4+1]=v.y;
        zs[ty*8+i][tx*4+2]=v.z; zs[ty*8+i][tx*4+3]=v.w;
        if (m < N_NODES) *(float4*)&z[(size_t)m*DEMB + tx*4] = v;
    }
    #pragma unroll
    for (int i=0;i<8;i++){
        int lin = t + 256*i;
        int r = lin >> 5, c = lin & 31;
        W1s[r][c] = dec_W1[(size_t)r*FH + c];
    }
    __syncthreads();

    // ---- phase 2: d tile ----
    float acc2[8][2];
    #pragma unroll
    for (int i=0;i<8;i++){ acc2[i][0]=0.f; acc2[i][1]=0.f; }
    #pragma unroll 8
    for (int k=0;k<DEMB;k++){
        float rb0 = W1s[k][tx*2], rb1 = W1s[k][tx*2+1];
        #pragma unroll
        for (int i=0;i<8;i++){
            float ra = zs[ty*8+i][k];
            acc2[i][0] += ra*rb0;
            acc2[i][1] += ra*rb1;
        }
    }
    const float b0 = dec_b1[tx*2], b1 = dec_b1[tx*2+1];
    #pragma unroll
    for (int i=0;i<8;i++){
        int m = m0 + ty*8 + i;
        if (m < N_NODES)
            *(float2*)&g_d[(size_t)m*FH + tx*2] =
                make_float2(fmaxf(acc2[i][0]+b0,0.f), fmaxf(acc2[i][1]+b1,0.f));
    }
}

// ---------------- CSR build --------------------------------------------------
__global__ void count_kernel(const int* __restrict__ ei){
    int e = blockIdx.x*blockDim.x+threadIdx.x;
    if (e<N_EDGES) atomicAdd(&g_deg[ei[N_EDGES+e]],1);
}
__global__ void scan_kernel(){
    __shared__ int sm[1024];
    int t = threadIdx.x;
    const int CH = (N_NODES + 1023)/1024;   // 30
    int base = t*CH;
    int s=0;
    for (int i=0;i<CH;i++){ int idx=base+i; if(idx<N_NODES) s+=g_deg[idx]; }
    sm[t]=s; __syncthreads();
    for (int st=1; st<1024; st<<=1){
        int v = (t>=st)? sm[t-st]:0;
        __syncthreads();
        sm[t]+=v;
        __syncthreads();
    }
    int run = sm[t]-s;                      // exclusive prefix
    for (int i=0;i<CH;i++){
        int idx=base+i;
        if (idx<N_NODES){ g_off[idx]=run; g_cur[idx]=run; run+=g_deg[idx]; }
    }
    if (t==1023) g_off[N_NODES]=sm[1023];
}
__global__ void scatter_kernel(const int* __restrict__ ei){
    int e = blockIdx.x*blockDim.x+threadIdx.x;
    if (e<N_EDGES){
        int d = ei[N_EDGES+e];
        int p = atomicAdd(&g_cur[d],1);
        g_srcs[p] = ei[e];
    }
}

// ---------------- fused softmax + aggregate per dst node --------------------
// No max subtraction: alpha = exp(l)/sum(exp(l)) is identical, logits are O(1).
__global__ void agg_kernel(const float* __restrict__ bias_gat)
{
    const int node = blockIdx.x;
    const int t    = threadIdx.x;
    const int head = t >> 5;

    __shared__ int   s_src[64];
    __shared__ float s_p[64][NH];
    __shared__ float s_ps[NH];
    __shared__ float red[256];
    __shared__ float s_den[NH];

    const int off = g_off[node];
    const int deg = g_off[node+1]-off;

    float adv[NH];
    #pragma unroll
    for (int h=0;h<NH;h++) adv[h]=g_ad[node*NH+h];

    if (t<NH){
        float l = g_as[node*NH+t] + adv[t];
        l = (l>0.f) ? l : NEG*l;
        s_ps[t] = expf(l);           // self-loop weight
    }
    __syncthreads();

    float acc  = g_h[(size_t)node*HF + t] * s_ps[head];   // self loop message
    float dloc = 0.f;
    for (int c0=0; c0<deg; c0+=64){
        int nc = min(64, deg-c0);
        if (t<nc) s_src[t] = g_srcs[off+c0+t];
        __syncthreads();
        for (int pr=t; pr<nc*NH; pr+=256){
            int e = pr>>3, h = pr&7;
            int s = s_src[e];
            float l = g_as[s*NH+h] + adv[h];
            l = (l>0.f) ? l : NEG*l;
            float p = expf(l);
            s_p[e][h]=p;
            dloc += p;               // partial for head (t&7)
        }
        __syncthreads();
        #pragma unroll 4
        for (int e=0;e<nc;e++){
            acc += g_h[(size_t)s_src[e]*HF + t] * s_p[e][head];
        }
        __syncthreads();
    }

    red[t]=dloc; __syncthreads();
    if (t<NH){
        float d = s_ps[t];           // self-loop term in denominator
        #pragma unroll
        for (int j=0;j<32;j++) d += red[t+8*j];
        s_den[t]=d;
    }
    __syncthreads();

    float v = acc / s_den[head] + bias_gat[t];
    g_gat[(size_t)node*HF + t] = fmaxf(v, 0.f);
}

// ---------------- launch -----------------------------------------------------
extern "C" void kernel_launch(void* const* d_in, const int* in_sizes, int n_in,
                              void* d_out, int out_size)
{
    const float* x        = (const float*)d_in[0];
    const int*   ei       = (const int*)  d_in[1];
    const float* W        = (const float*)d_in[3];
    const float* att_src  = (const float*)d_in[4];
    const float* att_dst  = (const float*)d_in[5];
    const float* bias_gat = (const float*)d_in[6];
    const float* emb_W    = (const float*)d_in[7];
    const float* emb_b    = (const float*)d_in[8];
    const float* dec_W1   = (const float*)d_in[9];
    const float* dec_b1   = (const float*)d_in[10];
    const float* dec_W2   = (const float*)d_in[11];
    const float* dec_b2   = (const float*)d_in[12];

    float* recon = (float*)d_out;                              // [N, DIN]
    float* z     = (float*)d_out + (size_t)N_NODES*DIN;        // [N, DEMB]

    float* dp;
    cudaGetSymbolAddress((void**)&dp, g_d);

    cudaFuncSetAttribute(gemm1_mma_kernel,
                         cudaFuncAttributeMaxDynamicSharedMemorySize, GSMT);

    const int MB = (N_NODES + 127)/128;   // 235

    // 0) bf16 3-split operand prep (+ g_deg zeroing inside build_wB)
    split_x_kernel<<<(int)(((size_t)N_PAD*KSEC/8 + 255)/256), 256>>>(x);
    build_wB_kernel<<<(HF*KTOT + 255)/256, 256>>>(W);
    // 1) h = x @ W via mma.sync bf16x3 (+ fused a_s/a_d)
    gemm1_mma_kernel<<<dim3(2, MB), 256, GSMT>>>(att_src, att_dst);
    // 2) CSR by dst
    count_kernel  <<<(N_EDGES+255)/256,256>>>(ei);
    scan_kernel   <<<1,1024>>>();
    scatter_kernel<<<(N_EDGES+255)/256,256>>>(ei);
    // 3) attention softmax + aggregate + bias + relu
    agg_kernel<<<N_NODES,256>>>(bias_gat);
    // 4+5) fused z and d
    zd_kernel<<<MB, 256>>>(emb_W, emb_b, dec_W1, dec_b1, z);
    // 6) recon = d @ dec_W2 + dec_b2   [30000,32] x [32,1000]
    sgemm_kernel<128,64,32,8,4,0,1><<<dim3((DIN+63)/64,MB),256>>>(dp, dec_W2, dec_b2,
                                                                  recon,
                                                                  N_NODES, DIN, FH);
}

// round 9
// speedup vs baseline: 1.4915x; 1.1204x over previous
#include <cuda_runtime.h>
#include <cuda_bf16.h>
#include <cstdint>

#define N_NODES 30000
#define N_PAD   30080      // 235 * 128
#define N_EDGES 480000
#define DIN     1000
#define KSEC    1024       // padded section K
#define KTOT    3072       // 3 sections
#define NH      8
#define FH      32
#define HF      256        // NH*FH
#define DEMB    64
#define NEG     0.2f

// ---------------- scratch (device globals; no allocation allowed) ----------
__device__ __nv_bfloat16 g_xhi[(size_t)N_PAD*KSEC];
__device__ __nv_bfloat16 g_xlo[(size_t)N_PAD*KSEC];
__device__ __nv_bfloat16 g_wB [(size_t)HF*KTOT];    // B' [N=256][K=3072] K-major
__device__ float g_h   [(size_t)N_NODES*HF];   // x@W
__device__ float g_as  [N_NODES*NH];
__device__ float g_ad  [N_NODES*NH];
__device__ int   g_deg [N_NODES];
__device__ int   g_off [N_NODES+1];
__device__ int   g_cur [N_NODES];
__device__ int   g_srcs[N_EDGES];              // src ids sorted by dst
__device__ float g_gat [(size_t)N_NODES*HF];   // relu(GAT out + bias)
// recon operands (bf16x3): A' rows [d_hi | d_lo | d_hi], B' rows [w_hi|w_hi|w_lo]
__device__ __nv_bfloat16 g_dB [(size_t)N_PAD*96];
__device__ __nv_bfloat16 g_w2B[(size_t)1024*96];

// ======================= helpers ============================================
__device__ __forceinline__ uint32_t smem_to_u32(const void* p) {
    uint32_t a;
    asm("{ .reg .u64 t; cvta.to.shared.u64 t, %1; cvt.u32.u64 %0, t; }"
        : "=r"(a) : "l"(p));
    return a;
}
__device__ __forceinline__ void cpasync16(uint32_t saddr, const void* gp) {
    asm volatile("cp.async.cg.shared.global [%0], [%1], 16;" :: "r"(saddr), "l"(gp));
}
__device__ __forceinline__ void ldm_x4(uint32_t& r0, uint32_t& r1,
                                       uint32_t& r2, uint32_t& r3, uint32_t a) {
    asm volatile("ldmatrix.sync.aligned.m8n8.x4.shared.b16 {%0,%1,%2,%3}, [%4];"
                 : "=r"(r0), "=r"(r1), "=r"(r2), "=r"(r3) : "r"(a));
}
__device__ __forceinline__ void mma_bf16(float* c, const uint32_t* a,
                                         uint32_t b0, uint32_t b1) {
    asm volatile(
        "mma.sync.aligned.m16n8k16.row.col.f32.bf16.bf16.f32 "
        "{%0,%1,%2,%3}, {%4,%5,%6,%7}, {%8,%9}, {%0,%1,%2,%3};"
        : "+f"(c[0]), "+f"(c[1]), "+f"(c[2]), "+f"(c[3])
        : "r"(a[0]), "r"(a[1]), "r"(a[2]), "r"(a[3]), "r"(b0), "r"(b1));
}
__device__ __forceinline__ uint32_t pack_bf16x2(float a, float b) {
    __nv_bfloat16 ha = __float2bfloat16(a), hb = __float2bfloat16(b);
    return (uint32_t)__bfloat16_as_ushort(ha) |
           ((uint32_t)__bfloat16_as_ushort(hb) << 16);
}

// ======================= split / pack kernels ===============================
__global__ void split_x_kernel(const float* __restrict__ x) {
    size_t g8 = ((size_t)blockIdx.x * blockDim.x + threadIdx.x);
    if (g8 >= (size_t)N_PAD * KSEC / 8) return;
    size_t idx = g8 * 8;
    int r  = (int)(idx >> 10);
    int c0 = (int)(idx & 1023);
    float v[8];
    if (r < N_NODES && c0 + 7 < DIN) {
        const float4 f0 = *(const float4*)&x[(size_t)r * DIN + c0];
        const float4 f1 = *(const float4*)&x[(size_t)r * DIN + c0 + 4];
        v[0]=f0.x; v[1]=f0.y; v[2]=f0.z; v[3]=f0.w;
        v[4]=f1.x; v[5]=f1.y; v[6]=f1.z; v[7]=f1.w;
    } else {
        #pragma unroll
        for (int i = 0; i < 8; i++) {
            int c = c0 + i;
            v[i] = (r < N_NODES && c < DIN) ? x[(size_t)r * DIN + c] : 0.f;
        }
    }
    __nv_bfloat16 hi[8], lo[8];
    #pragma unroll
    for (int i = 0; i < 8; i++) {
        hi[i] = __float2bfloat16(v[i]);
        lo[i] = __float2bfloat16(v[i] - __bfloat162float(hi[i]));
    }
    *(uint4*)&g_xhi[idx] = *(const uint4*)hi;
    *(uint4*)&g_xlo[idx] = *(const uint4*)lo;
}
// packs g_wB, g_w2B; also zeroes g_deg
__global__ void build_wB_kernel(const float* __restrict__ W,
                                const float* __restrict__ W2) {
    int idx = blockIdx.x * blockDim.x + threadIdx.x;       // over 256*3072
    if (idx < N_NODES) g_deg[idx] = 0;
    if (idx < 1024 * 96) {
        int n  = idx / 96;
        int kk = idx - n * 96;
        int sec = kk >> 5, k = kk & 31;
        float v = (n < DIN) ? W2[(size_t)k * DIN + n] : 0.f;
        __nv_bfloat16 hi = __float2bfloat16(v);
        g_w2B[idx] = (sec == 2) ? __float2bfloat16(v - __bfloat162float(hi)) : hi;
    }
    if (idx >= HF * KTOT) return;
    int n  = idx / KTOT;
    int kk = idx % KTOT;
    int s  = kk >> 10;
    int k  = kk & 1023;
    float v = (k < DIN) ? W[(size_t)k * HF + n] : 0.f;
    __nv_bfloat16 hi = __float2bfloat16(v);
    g_wB[idx] = (s == 2) ? __float2bfloat16(v - __bfloat162float(hi)) : hi;
}

// ======================= bf16 mma.sync GEMM1 (+fused att) ===================
// BM=128 BN=128 BK=32, 256 threads, 8 warps (4 m x 2 n), warp tile 32x64.
// 3 slots / 2 preloads / single barrier per chunk.
#define BKC  32
#define LDSM 40           // BKC + 8 pad elements (80B row stride)
#define NCH  96           // 3072/32
#define STGB 20480u       // bytes per stage (A 10240 + B 10240)
#define GSMT (3u*STGB)    // 61440

__global__ void __launch_bounds__(256, 2) gemm1_mma_kernel(
    const float* __restrict__ att_src, const float* __restrict__ att_dst)
{
    extern __shared__ char gsm[];
    const uint32_t sb = smem_to_u32(gsm);
    const int t    = threadIdx.x;
    const int lane = t & 31;
    const int wid  = t >> 5;
    const int wm   = (wid & 3) * 32;
    const int wn   = (wid >> 2) * 64;
    const int m0   = blockIdx.y * 128;
    const int n0   = blockIdx.x * 128;

    float acc[2][8][4];
    #pragma unroll
    for (int i = 0; i < 2; i++)
        #pragma unroll
        for (int j = 0; j < 8; j++)
            #pragma unroll
            for (int q = 0; q < 4; q++) acc[i][j][q] = 0.f;

    const int a_r = (lane & 7) + ((lane >> 3) & 1) * 8;
    const int a_c = (lane >> 4) * 8;
    const int b_r = ((lane >> 4) & 1) * 8 + (lane & 7);
    const int b_c = ((lane >> 3) & 1) * 8;

    auto sAaddr = [&](int s, int r, int c) -> uint32_t {
        return sb + (uint32_t)s * STGB + (uint32_t)r * (LDSM * 2) + (uint32_t)c * 2;
    };
    auto sBaddr = [&](int s, int r, int c) -> uint32_t {
        return sb + (uint32_t)s * STGB + 10240u + (uint32_t)r * (LDSM * 2) + (uint32_t)c * 2;
    };

    auto load_stage = [&](int s, int c) {
        const int kp  = c * BKC;
        const int sec = kp >> 10;
        const int ko  = kp & 1023;
        const __nv_bfloat16* Abase = ((sec == 1) ? g_xlo : g_xhi)
                                     + (size_t)m0 * KSEC + ko;
        const __nv_bfloat16* Bbase = g_wB + (size_t)n0 * KTOT + kp;
        #pragma unroll
        for (int i = 0; i < 2; i++) {
            int u  = t + 256 * i;
            int r  = u >> 2;
            int ch = (u & 3) * 8;
            cpasync16(sAaddr(s, r, ch), Abase + (size_t)r * KSEC + ch);
            cpasync16(sBaddr(s, r, ch), Bbase + (size_t)r * KTOT + ch);
        }
    };

    load_stage(0, 0);
    asm volatile("cp.async.commit_group;" ::: "memory");
    load_stage(1, 1);
    asm volatile("cp.async.commit_group;" ::: "memory");

    for (int c = 0; c < NCH; c++) {
        const int s = c % 3;
        asm volatile("cp.async.wait_group 1;" ::: "memory");
        __syncthreads();
        if (c + 2 < NCH) load_stage((c + 2) % 3, c + 2);
        asm volatile("cp.async.commit_group;" ::: "memory");

        #pragma unroll
        for (int ks = 0; ks < 2; ks++) {
            const int kb = ks * 16;
            uint32_t a[2][4];
            #pragma unroll
            for (int mt = 0; mt < 2; mt++)
                ldm_x4(a[mt][0], a[mt][1], a[mt][2], a[mt][3],
                       sAaddr(s, wm + mt * 16 + a_r, kb + a_c));
            #pragma unroll
            for (int nt4 = 0; nt4 < 4; nt4++) {
                uint32_t b0, b1, b2, b3;
                ldm_x4(b0, b1, b2, b3, sBaddr(s, wn + nt4 * 16 + b_r, kb + b_c));
                #pragma unroll
                for (int mt = 0; mt < 2; mt++) {
                    mma_bf16(acc[mt][nt4 * 2 + 0], a[mt], b0, b1);
                    mma_bf16(acc[mt][nt4 * 2 + 1], a[mt], b2, b3);
                }
            }
        }
    }

    // ---- epilogue 1: write C fragments to g_h ----
    #pragma unroll
    for (int mt = 0; mt < 2; mt++) {
        const int r0 = m0 + wm + mt * 16 + (lane >> 2);
        #pragma unroll
        for (int nt = 0; nt < 8; nt++) {
            const int cc = n0 + wn + nt * 8 + (lane & 3) * 2;
            if (r0 < N_NODES)
                *(float2*)&g_h[(size_t)r0 * HF + cc] =
                    make_float2(acc[mt][nt][0], acc[mt][nt][1]);
            if (r0 + 8 < N_NODES)
                *(float2*)&g_h[(size_t)(r0 + 8) * HF + cc] =
                    make_float2(acc[mt][nt][2], acc[mt][nt][3]);
        }
    }

    // ---- epilogue 2: fused a_s / a_d ----
    {
        const int head0 = (n0 + wn) >> 5;
        float2 sv[8], dv[8];
        #pragma unroll
        for (int nt = 0; nt < 8; nt++) {
            const int cc = n0 + wn + nt * 8 + (lane & 3) * 2;
            sv[nt] = *(const float2*)&att_src[cc];
            dv[nt] = *(const float2*)&att_dst[cc];
        }
        #pragma unroll
        for (int mt = 0; mt < 2; mt++) {
            #pragma unroll
            for (int hf = 0; hf < 2; hf++) {
                float vs0 = 0.f, vd0 = 0.f, vs1 = 0.f, vd1 = 0.f;
                #pragma unroll
                for (int j = 0; j < 4; j++) {
                    const int nt = hf * 4 + j;
                    vs0 += acc[mt][nt][0] * sv[nt].x + acc[mt][nt][1] * sv[nt].y;
                    vd0 += acc[mt][nt][0] * dv[nt].x + acc[mt][nt][1] * dv[nt].y;
                    vs1 += acc[mt][nt][2] * sv[nt].x + acc[mt][nt][3] * sv[nt].y;
                    vd1 += acc[mt][nt][2] * dv[nt].x + acc[mt][nt][3] * dv[nt].y;
                }
                vs0 += __shfl_xor_sync(0xffffffffu, vs0, 1);
                vs0 += __shfl_xor_sync(0xffffffffu, vs0, 2);
                vd0 += __shfl_xor_sync(0xffffffffu, vd0, 1);
                vd0 += __shfl_xor_sync(0xffffffffu, vd0, 2);
                vs1 += __shfl_xor_sync(0xffffffffu, vs1, 1);
                vs1 += __shfl_xor_sync(0xffffffffu, vs1, 2);
                vd1 += __shfl_xor_sync(0xffffffffu, vd1, 1);
                vd1 += __shfl_xor_sync(0xffffffffu, vd1, 2);
                if ((lane & 3) == 0) {
                    const int r0 = m0 + wm + mt * 16 + (lane >> 2);
                    const int h  = head0 + hf;
                    if (r0 < N_NODES)     { g_as[r0*NH + h] = vs0; g_ad[r0*NH + h] = vd0; }
                    if (r0 + 8 < N_NODES) { g_as[(r0+8)*NH + h] = vs1; g_ad[(r0+8)*NH + h] = vd1; }
                }
            }
        }
    }
}

// ======================= recon bf16 mma GEMM ================================
// recon[30000,1000] = A'[30080,96] @ B'[1024,96]^T + dec_b2, bf16x3 terms.
// BM=128 BN=128, single-shot load (K=96), 6 mma sub-chunks.
#define RLD  104          // 96 + 8 pad (208B row stride; mod 128 == 80)
#define RSMT (2u*128u*RLD*2u)   // 53248

__global__ void __launch_bounds__(256) recon_mma_kernel(
    const float* __restrict__ bias, float* __restrict__ recon)
{
    extern __shared__ char rsm[];
    const uint32_t sb = smem_to_u32(rsm);
    const int t    = threadIdx.x;
    const int lane = t & 31;
    const int wid  = t >> 5;
    const int wm   = (wid & 3) * 32;
    const int wn   = (wid >> 2) * 64;
    const int m0   = blockIdx.y * 128;
    const int n0   = blockIdx.x * 128;

    auto sAaddr = [&](int r, int c) -> uint32_t {
        return sb + (uint32_t)r * (RLD * 2) + (uint32_t)c * 2;
    };
    auto sBaddr = [&](int r, int c) -> uint32_t {
        return sb + 128u * RLD * 2u + (uint32_t)r * (RLD * 2) + (uint32_t)c * 2;
    };

    // load A,B tiles: 128 rows x 96 cols = 12 x 16B chunks per row, 1536 chunks
    #pragma unroll
    for (int i = 0; i < 6; i++) {
        int u  = t + 256 * i;
        int r  = u / 12;
        int ch = (u % 12) * 8;
        cpasync16(sAaddr(r, ch), g_dB  + (size_t)(m0 + r) * 96 + ch);
        cpasync16(sBaddr(r, ch), g_w2B + (size_t)(n0 + r) * 96 + ch);
    }
    asm volatile("cp.async.commit_group;" ::: "memory");

    float acc[2][8][4];
    #pragma unroll
    for (int i = 0; i < 2; i++)
        #pragma unroll
        for (int j = 0; j < 8; j++)
            #pragma unroll
            for (int q = 0; q < 4; q++) acc[i][j][q] = 0.f;

    const int a_r = (lane & 7) + ((lane >> 3) & 1) * 8;
    const int a_c = (lane >> 4) * 8;
    const int b_r = ((lane >> 4) & 1) * 8 + (lane & 7);
    const int b_c = ((lane >> 3) & 1) * 8;

    asm volatile("cp.async.wait_group 0;" ::: "memory");
    __syncthreads();

    #pragma unroll
    for (int ks = 0; ks < 6; ks++) {
        const int kb = ks * 16;
        uint32_t a[2][4];
        #pragma unroll
        for (int mt = 0; mt < 2; mt++)
            ldm_x4(a[mt][0], a[mt][1], a[mt][2], a[mt][3],
                   sAaddr(wm + mt * 16 + a_r, kb + a_c));
        #pragma unroll
        for (int nt4 = 0; nt4 < 4; nt4++) {
            uint32_t b0, b1, b2, b3;
            ldm_x4(b0, b1, b2, b3, sBaddr(wn + nt4 * 16 + b_r, kb + b_c));
            #pragma unroll
            for (int mt = 0; mt < 2; mt++) {
                mma_bf16(acc[mt][nt4 * 2 + 0], a[mt], b0, b1);
                mma_bf16(acc[mt][nt4 * 2 + 1], a[mt], b2, b3);
            }
        }
    }

    #pragma unroll
    for (int mt = 0; mt < 2; mt++) {
        const int r0 = m0 + wm + mt * 16 + (lane >> 2);
        #pragma unroll
        for (int nt = 0; nt < 8; nt++) {
            const int cc = n0 + wn + nt * 8 + (lane & 3) * 2;
            if (cc >= DIN) continue;
            const float2 bv = *(const float2*)&bias[cc];
            if (r0 < N_NODES)
                *(float2*)&recon[(size_t)r0 * DIN + cc] =
                    make_float2(acc[mt][nt][0] + bv.x, acc[mt][nt][1] + bv.y);
            if (r0 + 8 < N_NODES)
                *(float2*)&recon[(size_t)(r0 + 8) * DIN + cc] =
                    make_float2(acc[mt][nt][2] + bv.x, acc[mt][nt][3] + bv.y);
        }
    }
}

// ---------------- fused z + d kernel (d emitted as bf16x3 A-matrix) ---------
__global__ void __launch_bounds__(256) zd_kernel(
    const float* __restrict__ emb_W, const float* __restrict__ emb_b,
    const float* __restrict__ dec_W1, const float* __restrict__ dec_b1,
    float* __restrict__ z)
{
    __shared__ float sbuf[10432];
    float (*As)[132] = (float(*)[132])sbuf;            // 32 x 132 (phase 1)
    float (*Bs)[68]  = (float(*)[68])(sbuf + 4224);    // 32 x 68  (phase 1)
    float (*zs)[65]  = (float(*)[65])sbuf;             // 128 x 65 (phase 2)
    float (*W1s)[33] = (float(*)[33])(sbuf + 8320);    // 64 x 33  (phase 2)

    const int t  = threadIdx.x;
    const int tx = t & 15, ty = t >> 4;
    const int m0 = blockIdx.x * 128;

    float acc[8][4];
    #pragma unroll
    for (int i=0;i<8;i++)
        #pragma unroll
        for (int j=0;j<4;j++) acc[i][j]=0.f;

    for (int k0=0;k0<HF;k0+=32) {
        #pragma unroll
        for (int i=0;i<16;i++){
            int lin = t + 256*i;
            int r = lin >> 5, c = lin & 31;
            As[c][r] = (m0+r < N_NODES) ? g_gat[(size_t)(m0+r)*HF + k0+c] : 0.f;
        }
        #pragma unroll
        for (int i=0;i<8;i++){
            int lin = t + 256*i;
            int r = lin >> 6, c = lin & 63;
            Bs[r][c] = emb_W[(size_t)(k0+r)*DEMB + c];
        }
        __syncthreads();
        #pragma unroll
        for (int k=0;k<32;k++){
            float ra[8], rb[4];
            #pragma unroll
            for (int i=0;i<8;i++) ra[i]=As[k][ty*8+i];
            #pragma unroll
            for (int j=0;j<4;j++) rb[j]=Bs[k][tx*4+j];
            #pragma unroll
            for (int i=0;i<8;i++)
                #pragma unroll
                for (int j=0;j<4;j++) acc[i][j] += ra[i]*rb[j];
        }
        __syncthreads();
    }

    const float4 bz = *(const float4*)&emb_b[tx*4];
    #pragma unroll
    for (int i=0;i<8;i++){
        int m = m0 + ty*8 + i;
        float4 v = make_float4(acc[i][0]+bz.x, acc[i][1]+bz.y,
                               acc[i][2]+bz.z, acc[i][3]+bz.w);
        zs[ty*8+i][tx*4+0]=v.x; zs[ty*8+i][tx*4+1]=v.y;
        zs[ty*8+i][tx*4+2]=v.z; zs[ty*8+i][tx*4+3]=v.w;
        if (m < N_NODES) *(float4*)&z[(size_t)m*DEMB + tx*4] = v;
    }
    #pragma unroll
    for (int i=0;i<8;i++){
        int lin = t + 256*i;
        int r = lin >> 5, c = lin & 31;
        W1s[r][c] = dec_W1[(size_t)r*FH + c];
    }
    __syncthreads();

    float acc2[8][2];
    #pragma unroll
    for (int i=0;i<8;i++){ acc2[i][0]=0.f; acc2[i][1]=0.f; }
    #pragma unroll 8
    for (int k=0;k<DEMB;k++){
        float rb0 = W1s[k][tx*2], rb1 = W1s[k][tx*2+1];
        #pragma unroll
        for (int i=0;i<8;i++){
            float ra = zs[ty*8+i][k];
            acc2[i][0] += ra*rb0;
            acc2[i][1] += ra*rb1;
        }
    }
    const float b0 = dec_b1[tx*2], b1 = dec_b1[tx*2+1];
    const int k2 = tx*2;
    #pragma unroll
    for (int i=0;i<8;i++){
        int m = m0 + ty*8 + i;
        if (m < N_NODES){
            float v0 = fmaxf(acc2[i][0]+b0, 0.f);
            float v1 = fmaxf(acc2[i][1]+b1, 0.f);
            __nv_bfloat16 h0 = __float2bfloat16(v0);
            __nv_bfloat16 h1 = __float2bfloat16(v1);
            uint32_t hi2 = (uint32_t)__bfloat16_as_ushort(h0) |
                           ((uint32_t)__bfloat16_as_ushort(h1) << 16);
            uint32_t lo2 = pack_bf16x2(v0 - __bfloat162float(h0),
                                       v1 - __bfloat162float(h1));
            size_t base = (size_t)m * 96;
            *(uint32_t*)&g_dB[base + k2]      = hi2;   // section 0: d_hi
            *(uint32_t*)&g_dB[base + 32 + k2] = lo2;   // section 1: d_lo
            *(uint32_t*)&g_dB[base + 64 + k2] = hi2;   // section 2: d_hi
        }
    }
}

// ---------------- CSR build --------------------------------------------------
__global__ void count_kernel(const int* __restrict__ ei){
    int e = blockIdx.x*blockDim.x+threadIdx.x;
    if (e<N_EDGES) atomicAdd(&g_deg[ei[N_EDGES+e]],1);
}
__global__ void scan_kernel(){
    __shared__ int sm[1024];
    int t = threadIdx.x;
    const int CH = (N_NODES + 1023)/1024;   // 30
    int base = t*CH;
    int s=0;
    for (int i=0;i<CH;i++){ int idx=base+i; if(idx<N_NODES) s+=g_deg[idx]; }
    sm[t]=s; __syncthreads();
    for (int st=1; st<1024; st<<=1){
        int v = (t>=st)? sm[t-st]:0;
        __syncthreads();
        sm[t]+=v;
        __syncthreads();
    }
    int run = sm[t]-s;
    for (int i=0;i<CH;i++){
        int idx=base+i;
        if (idx<N_NODES){ g_off[idx]=run; g_cur[idx]=run; run+=g_deg[idx]; }
    }
    if (t==1023) g_off[N_NODES]=sm[1023];
}
__global__ void scatter_kernel(const int* __restrict__ ei){
    int e = blockIdx.x*blockDim.x+threadIdx.x;
    if (e<N_EDGES){
        int d = ei[N_EDGES+e];
        int p = atomicAdd(&g_cur[d],1);
        g_srcs[p] = ei[e];
    }
}

// ---------------- fused softmax + aggregate per dst node --------------------
__global__ void agg_kernel(const float* __restrict__ bias_gat)
{
    const int node = blockIdx.x;
    const int t    = threadIdx.x;
    const int head = t >> 5;

    __shared__ int   s_src[64];
    __shared__ float s_p[64][NH];
    __shared__ float s_ps[NH];
    __shared__ float red[256];
    __shared__ float s_den[NH];

    const int off = g_off[node];
    const int deg = g_off[node+1]-off;

    float adv[NH];
    #pragma unroll
    for (int h=0;h<NH;h++) adv[h]=g_ad[node*NH+h];

    if (t<NH){
        float l = g_as[node*NH+t] + adv[t];
        l = (l>0.f) ? l : NEG*l;
        s_ps[t] = expf(l);
    }
    __syncthreads();

    float acc  = g_h[(size_t)node*HF + t] * s_ps[head];
    float dloc = 0.f;
    for (int c0=0; c0<deg; c0+=64){
        int nc = min(64, deg-c0);
        if (t<nc) s_src[t] = g_srcs[off+c0+t];
        __syncthreads();
        for (int pr=t; pr<nc*NH; pr+=256){
            int e = pr>>3, h = pr&7;
            int s = s_src[e];
            float l = g_as[s*NH+h] + adv[h];
            l = (l>0.f) ? l : NEG*l;
            float p = expf(l);
            s_p[e][h]=p;
            dloc += p;
        }
        __syncthreads();
        #pragma unroll 4
        for (int e=0;e<nc;e++){
            acc += g_h[(size_t)s_src[e]*HF + t] * s_p[e][head];
        }
        __syncthreads();
    }

    red[t]=dloc; __syncthreads();
    if (t<NH){
        float d = s_ps[t];
        #pragma unroll
        for (int j=0;j<32;j++) d += red[t+8*j];
        s_den[t]=d;
    }
    __syncthreads();

    float v = acc / s_den[head] + bias_gat[t];
    g_gat[(size_t)node*HF + t] = fmaxf(v, 0.f);
}

// ---------------- launch -----------------------------------------------------
extern "C" void kernel_launch(void* const* d_in, const int* in_sizes, int n_in,
                              void* d_out, int out_size)
{
    const float* x        = (const float*)d_in[0];
    const int*   ei       = (const int*)  d_in[1];
    const float* W        = (const float*)d_in[3];
    const float* att_src  = (const float*)d_in[4];
    const float* att_dst  = (const float*)d_in[5];
    const float* bias_gat = (const float*)d_in[6];
    const float* emb_W    = (const float*)d_in[7];
    const float* emb_b    = (const float*)d_in[8];
    const float* dec_W1   = (const float*)d_in[9];
    const float* dec_b1   = (const float*)d_in[10];
    const float* dec_W2   = (const float*)d_in[11];
    const float* dec_b2   = (const float*)d_in[12];

    float* recon = (float*)d_out;                              // [N, DIN]
    float* z     = (float*)d_out + (size_t)N_NODES*DIN;        // [N, DEMB]

    cudaFuncSetAttribute(gemm1_mma_kernel,
                         cudaFuncAttributeMaxDynamicSharedMemorySize, GSMT);
    cudaFuncSetAttribute(recon_mma_kernel,
                         cudaFuncAttributeMaxDynamicSharedMemorySize, RSMT);

    const int MB = (N_NODES + 127)/128;   // 235

    // 0) bf16 3-split operand prep (+ g_deg zero, + W2 pack)
    split_x_kernel<<<(int)(((size_t)N_PAD*KSEC/8 + 255)/256), 256>>>(x);
    build_wB_kernel<<<(HF*KTOT + 255)/256, 256>>>(W, dec_W2);
    // 1) h = x @ W via mma.sync bf16x3 (+ fused a_s/a_d)
    gemm1_mma_kernel<<<dim3(2, MB), 256, GSMT>>>(att_src, att_dst);
    // 2) CSR by dst
    count_kernel  <<<(N_EDGES+255)/256,256>>>(ei);
    scan_kernel   <<<1,1024>>>();
    scatter_kernel<<<(N_EDGES+255)/256,256>>>(ei);
    // 3) attention softmax + aggregate + bias + relu
    agg_kernel<<<N_NODES,256>>>(bias_gat);
    // 4+5) fused z and d (d emitted as bf16x3)
    zd_kernel<<<MB, 256>>>(emb_W, emb_b, dec_W1, dec_b1, z);
    // 6) recon = d @ dec_W2 + dec_b2 via mma.sync bf16x3
    recon_mma_kernel<<<dim3(8, MB), 256, RSMT>>>(dec_b2, recon);
}

// round 10
// speedup vs baseline: 1.6255x; 1.0898x over previous
#include <cuda_runtime.h>
#include <cuda_bf16.h>
#include <cstdint>

#define N_NODES 30000
#define N_PAD   30080      // 235 * 128
#define N_EDGES 480000
#define DIN     1000
#define KSEC    1024       // padded section K
#define KTOT    3072       // 3 sections
#define NH      8
#define FH      32
#define HF      256        // NH*FH
#define DEMB    64
#define NEG     0.2f

// ---------------- scratch (device globals; no allocation allowed) ----------
__device__ __nv_bfloat16 g_xhi[(size_t)N_PAD*KSEC];
__device__ __nv_bfloat16 g_xlo[(size_t)N_PAD*KSEC];
__device__ __nv_bfloat16 g_wB [(size_t)HF*KTOT];    // B' [N=256][K=3072] K-major
__device__ float g_h   [(size_t)N_NODES*HF];   // x@W
__device__ float g_as  [N_NODES*NH];
__device__ float g_ad  [N_NODES*NH];
__device__ int   g_deg [N_NODES];
__device__ int   g_off [N_NODES+1];
__device__ int   g_cur [N_NODES];
__device__ int   g_srcs[N_EDGES];              // src ids sorted by dst
__device__ float g_gat [(size_t)N_NODES*HF];   // relu(GAT out + bias)
// recon operands (bf16x3): A' rows [d_hi | d_lo | d_hi], B' rows [w_hi|w_hi|w_lo]
__device__ __nv_bfloat16 g_dB [(size_t)N_PAD*96];
__device__ __nv_bfloat16 g_w2B[(size_t)1024*96];

// ======================= helpers ============================================
__device__ __forceinline__ uint32_t smem_to_u32(const void* p) {
    uint32_t a;
    asm("{ .reg .u64 t; cvta.to.shared.u64 t, %1; cvt.u32.u64 %0, t; }"
        : "=r"(a) : "l"(p));
    return a;
}
__device__ __forceinline__ void cpasync16(uint32_t saddr, const void* gp) {
    asm volatile("cp.async.cg.shared.global [%0], [%1], 16;" :: "r"(saddr), "l"(gp));
}
__device__ __forceinline__ void ldm_x4(uint32_t& r0, uint32_t& r1,
                                       uint32_t& r2, uint32_t& r3, uint32_t a) {
    asm volatile("ldmatrix.sync.aligned.m8n8.x4.shared.b16 {%0,%1,%2,%3}, [%4];"
                 : "=r"(r0), "=r"(r1), "=r"(r2), "=r"(r3) : "r"(a));
}
__device__ __forceinline__ void mma_bf16(float* c, const uint32_t* a,
                                         uint32_t b0, uint32_t b1) {
    asm volatile(
        "mma.sync.aligned.m16n8k16.row.col.f32.bf16.bf16.f32 "
        "{%0,%1,%2,%3}, {%4,%5,%6,%7}, {%8,%9}, {%0,%1,%2,%3};"
        : "+f"(c[0]), "+f"(c[1]), "+f"(c[2]), "+f"(c[3])
        : "r"(a[0]), "r"(a[1]), "r"(a[2]), "r"(a[3]), "r"(b0), "r"(b1));
}
__device__ __forceinline__ uint32_t pack_bf16x2(float a, float b) {
    __nv_bfloat16 ha = __float2bfloat16(a), hb = __float2bfloat16(b);
    return (uint32_t)__bfloat16_as_ushort(ha) |
           ((uint32_t)__bfloat16_as_ushort(hb) << 16);
}

// ======================= split / pack kernels ===============================
// 8 elems/thread; also zeroes g_deg (ordering: before build_wB's count pass)
__global__ void split_x_kernel(const float* __restrict__ x) {
    size_t g8 = ((size_t)blockIdx.x * blockDim.x + threadIdx.x);
    if (g8 < N_NODES) g_deg[g8] = 0;
    if (g8 >= (size_t)N_PAD * KSEC / 8) return;
    size_t idx = g8 * 8;
    int r  = (int)(idx >> 10);
    int c0 = (int)(idx & 1023);
    float v[8];
    if (r < N_NODES && c0 + 7 < DIN) {
        const float4 f0 = *(const float4*)&x[(size_t)r * DIN + c0];
        const float4 f1 = *(const float4*)&x[(size_t)r * DIN + c0 + 4];
        v[0]=f0.x; v[1]=f0.y; v[2]=f0.z; v[3]=f0.w;
        v[4]=f1.x; v[5]=f1.y; v[6]=f1.z; v[7]=f1.w;
    } else {
        #pragma unroll
        for (int i = 0; i < 8; i++) {
            int c = c0 + i;
            v[i] = (r < N_NODES && c < DIN) ? x[(size_t)r * DIN + c] : 0.f;
        }
    }
    __nv_bfloat16 hi[8], lo[8];
    #pragma unroll
    for (int i = 0; i < 8; i++) {
        hi[i] = __float2bfloat16(v[i]);
        lo[i] = __float2bfloat16(v[i] - __bfloat162float(hi[i]));
    }
    *(uint4*)&g_xhi[idx] = *(const uint4*)hi;
    *(uint4*)&g_xlo[idx] = *(const uint4*)lo;
}
// packs g_wB, g_w2B; also counts in-degrees (g_deg zeroed by split_x before)
__global__ void build_wB_kernel(const float* __restrict__ W,
                                const float* __restrict__ W2,
                                const int* __restrict__ ei) {
    int idx = blockIdx.x * blockDim.x + threadIdx.x;       // over 256*3072
    if (idx < N_EDGES) atomicAdd(&g_deg[ei[N_EDGES + idx]], 1);
    if (idx < 1024 * 96) {
        int n  = idx / 96;
        int kk = idx - n * 96;
        int sec = kk >> 5, k = kk & 31;
        float v = (n < DIN) ? W2[(size_t)k * DIN + n] : 0.f;
        __nv_bfloat16 hi = __float2bfloat16(v);
        g_w2B[idx] = (sec == 2) ? __float2bfloat16(v - __bfloat162float(hi)) : hi;
    }
    if (idx >= HF * KTOT) return;
    int n  = idx / KTOT;
    int kk = idx % KTOT;
    int s  = kk >> 10;
    int k  = kk & 1023;
    float v = (k < DIN) ? W[(size_t)k * HF + n] : 0.f;
    __nv_bfloat16 hi = __float2bfloat16(v);
    g_wB[idx] = (s == 2) ? __float2bfloat16(v - __bfloat162float(hi)) : hi;
}

// ======================= bf16 mma.sync GEMM1 (+fused att) ===================
// BM=128 BN=128 BK=32, 256 threads, 8 warps (4 m x 2 n), warp tile 32x64.
// 3 slots / 2 preloads / single barrier per chunk.
#define BKC  32
#define LDSM 40           // BKC + 8 pad elements (80B row stride)
#define NCH  96           // 3072/32
#define STGB 20480u       // bytes per stage (A 10240 + B 10240)
#define GSMT (3u*STGB)    // 61440

__global__ void __launch_bounds__(256, 2) gemm1_mma_kernel(
    const float* __restrict__ att_src, const float* __restrict__ att_dst)
{
    extern __shared__ char gsm[];
    const uint32_t sb = smem_to_u32(gsm);
    const int t    = threadIdx.x;
    const int lane = t & 31;
    const int wid  = t >> 5;
    const int wm   = (wid & 3) * 32;
    const int wn   = (wid >> 2) * 64;
    const int m0   = blockIdx.y * 128;
    const int n0   = blockIdx.x * 128;

    float acc[2][8][4];
    #pragma unroll
    for (int i = 0; i < 2; i++)
        #pragma unroll
        for (int j = 0; j < 8; j++)
            #pragma unroll
            for (int q = 0; q < 4; q++) acc[i][j][q] = 0.f;

    const int a_r = (lane & 7) + ((lane >> 3) & 1) * 8;
    const int a_c = (lane >> 4) * 8;
    const int b_r = ((lane >> 4) & 1) * 8 + (lane & 7);
    const int b_c = ((lane >> 3) & 1) * 8;

    auto sAaddr = [&](int s, int r, int c) -> uint32_t {
        return sb + (uint32_t)s * STGB + (uint32_t)r * (LDSM * 2) + (uint32_t)c * 2;
    };
    auto sBaddr = [&](int s, int r, int c) -> uint32_t {
        return sb + (uint32_t)s * STGB + 10240u + (uint32_t)r * (LDSM * 2) + (uint32_t)c * 2;
    };

    auto load_stage = [&](int s, int c) {
        const int kp  = c * BKC;
        const int sec = kp >> 10;
        const int ko  = kp & 1023;
        const __nv_bfloat16* Abase = ((sec == 1) ? g_xlo : g_xhi)
                                     + (size_t)m0 * KSEC + ko;
        const __nv_bfloat16* Bbase = g_wB + (size_t)n0 * KTOT + kp;
        #pragma unroll
        for (int i = 0; i < 2; i++) {
            int u  = t + 256 * i;
            int r  = u >> 2;
            int ch = (u & 3) * 8;
            cpasync16(sAaddr(s, r, ch), Abase + (size_t)r * KSEC + ch);
            cpasync16(sBaddr(s, r, ch), Bbase + (size_t)r * KTOT + ch);
        }
    };

    load_stage(0, 0);
    asm volatile("cp.async.commit_group;" ::: "memory");
    load_stage(1, 1);
    asm volatile("cp.async.commit_group;" ::: "memory");

    for (int c = 0; c < NCH; c++) {
        const int s = c % 3;
        asm volatile("cp.async.wait_group 1;" ::: "memory");
        __syncthreads();
        if (c + 2 < NCH) load_stage((c + 2) % 3, c + 2);
        asm volatile("cp.async.commit_group;" ::: "memory");

        #pragma unroll
        for (int ks = 0; ks < 2; ks++) {
            const int kb = ks * 16;
            uint32_t a[2][4];
            #pragma unroll
            for (int mt = 0; mt < 2; mt++)
                ldm_x4(a[mt][0], a[mt][1], a[mt][2], a[mt][3],
                       sAaddr(s, wm + mt * 16 + a_r, kb + a_c));
            #pragma unroll
            for (int nt4 = 0; nt4 < 4; nt4++) {
                uint32_t b0, b1, b2, b3;
                ldm_x4(b0, b1, b2, b3, sBaddr(s, wn + nt4 * 16 + b_r, kb + b_c));
                #pragma unroll
                for (int mt = 0; mt < 2; mt++) {
                    mma_bf16(acc[mt][nt4 * 2 + 0], a[mt], b0, b1);
                    mma_bf16(acc[mt][nt4 * 2 + 1], a[mt], b2, b3);
                }
            }
        }
    }

    // ---- epilogue 1: write C fragments to g_h ----
    #pragma unroll
    for (int mt = 0; mt < 2; mt++) {
        const int r0 = m0 + wm + mt * 16 + (lane >> 2);
        #pragma unroll
        for (int nt = 0; nt < 8; nt++) {
            const int cc = n0 + wn + nt * 8 + (lane & 3) * 2;
            if (r0 < N_NODES)
                *(float2*)&g_h[(size_t)r0 * HF + cc] =
                    make_float2(acc[mt][nt][0], acc[mt][nt][1]);
            if (r0 + 8 < N_NODES)
                *(float2*)&g_h[(size_t)(r0 + 8) * HF + cc] =
                    make_float2(acc[mt][nt][2], acc[mt][nt][3]);
        }
    }

    // ---- epilogue 2: fused a_s / a_d ----
    {
        const int head0 = (n0 + wn) >> 5;
        float2 sv[8], dv[8];
        #pragma unroll
        for (int nt = 0; nt < 8; nt++) {
            const int cc = n0 + wn + nt * 8 + (lane & 3) * 2;
            sv[nt] = *(const float2*)&att_src[cc];
            dv[nt] = *(const float2*)&att_dst[cc];
        }
        #pragma unroll
        for (int mt = 0; mt < 2; mt++) {
            #pragma unroll
            for (int hf = 0; hf < 2; hf++) {
                float vs0 = 0.f, vd0 = 0.f, vs1 = 0.f, vd1 = 0.f;
                #pragma unroll
                for (int j = 0; j < 4; j++) {
                    const int nt = hf * 4 + j;
                    vs0 += acc[mt][nt][0] * sv[nt].x + acc[mt][nt][1] * sv[nt].y;
                    vd0 += acc[mt][nt][0] * dv[nt].x + acc[mt][nt][1] * dv[nt].y;
                    vs1 += acc[mt][nt][2] * sv[nt].x + acc[mt][nt][3] * sv[nt].y;
                    vd1 += acc[mt][nt][2] * dv[nt].x + acc[mt][nt][3] * dv[nt].y;
                }
                vs0 += __shfl_xor_sync(0xffffffffu, vs0, 1);
                vs0 += __shfl_xor_sync(0xffffffffu, vs0, 2);
                vd0 += __shfl_xor_sync(0xffffffffu, vd0, 1);
                vd0 += __shfl_xor_sync(0xffffffffu, vd0, 2);
                vs1 += __shfl_xor_sync(0xffffffffu, vs1, 1);
                vs1 += __shfl_xor_sync(0xffffffffu, vs1, 2);
                vd1 += __shfl_xor_sync(0xffffffffu, vd1, 1);
                vd1 += __shfl_xor_sync(0xffffffffu, vd1, 2);
                if ((lane & 3) == 0) {
                    const int r0 = m0 + wm + mt * 16 + (lane >> 2);
                    const int h  = head0 + hf;
                    if (r0 < N_NODES)     { g_as[r0*NH + h] = vs0; g_ad[r0*NH + h] = vd0; }
                    if (r0 + 8 < N_NODES) { g_as[(r0+8)*NH + h] = vs1; g_ad[(r0+8)*NH + h] = vd1; }
                }
            }
        }
    }
}

// ======================= recon bf16 mma GEMM ================================
#define RLD  104          // 96 + 8 pad
#define RSMT (2u*128u*RLD*2u)   // 53248

__global__ void __launch_bounds__(256) recon_mma_kernel(
    const float* __restrict__ bias, float* __restrict__ recon)
{
    extern __shared__ char rsm[];
    const uint32_t sb = smem_to_u32(rsm);
    const int t    = threadIdx.x;
    const int lane = t & 31;
    const int wid  = t >> 5;
    const int wm   = (wid & 3) * 32;
    const int wn   = (wid >> 2) * 64;
    const int m0   = blockIdx.y * 128;
    const int n0   = blockIdx.x * 128;

    auto sAaddr = [&](int r, int c) -> uint32_t {
        return sb + (uint32_t)r * (RLD * 2) + (uint32_t)c * 2;
    };
    auto sBaddr = [&](int r, int c) -> uint32_t {
        return sb + 128u * RLD * 2u + (uint32_t)r * (RLD * 2) + (uint32_t)c * 2;
    };

    #pragma unroll
    for (int i = 0; i < 6; i++) {
        int u  = t + 256 * i;
        int r  = u / 12;
        int ch = (u % 12) * 8;
        cpasync16(sAaddr(r, ch), g_dB  + (size_t)(m0 + r) * 96 + ch);
        cpasync16(sBaddr(r, ch), g_w2B + (size_t)(n0 + r) * 96 + ch);
    }
    asm volatile("cp.async.commit_group;" ::: "memory");

    float acc[2][8][4];
    #pragma unroll
    for (int i = 0; i < 2; i++)
        #pragma unroll
        for (int j = 0; j < 8; j++)
            #pragma unroll
            for (int q = 0; q < 4; q++) acc[i][j][q] = 0.f;

    const int a_r = (lane & 7) + ((lane >> 3) & 1) * 8;
    const int a_c = (lane >> 4) * 8;
    const int b_r = ((lane >> 4) & 1) * 8 + (lane & 7);
    const int b_c = ((lane >> 3) & 1) * 8;

    asm volatile("cp.async.wait_group 0;" ::: "memory");
    __syncthreads();

    #pragma unroll
    for (int ks = 0; ks < 6; ks++) {
        const int kb = ks * 16;
        uint32_t a[2][4];
        #pragma unroll
        for (int mt = 0; mt < 2; mt++)
            ldm_x4(a[mt][0], a[mt][1], a[mt][2], a[mt][3],
                   sAaddr(wm + mt * 16 + a_r, kb + a_c));
        #pragma unroll
        for (int nt4 = 0; nt4 < 4; nt4++) {
            uint32_t b0, b1, b2, b3;
            ldm_x4(b0, b1, b2, b3, sBaddr(wn + nt4 * 16 + b_r, kb + b_c));
            #pragma unroll
            for (int mt = 0; mt < 2; mt++) {
                mma_bf16(acc[mt][nt4 * 2 + 0], a[mt], b0, b1);
                mma_bf16(acc[mt][nt4 * 2 + 1], a[mt], b2, b3);
            }
        }
    }

    #pragma unroll
    for (int mt = 0; mt < 2; mt++) {
        const int r0 = m0 + wm + mt * 16 + (lane >> 2);
        #pragma unroll
        for (int nt = 0; nt < 8; nt++) {
            const int cc = n0 + wn + nt * 8 + (lane & 3) * 2;
            if (cc >= DIN) continue;
            const float2 bv = *(const float2*)&bias[cc];
            if (r0 < N_NODES)
                *(float2*)&recon[(size_t)r0 * DIN + cc] =
                    make_float2(acc[mt][nt][0] + bv.x, acc[mt][nt][1] + bv.y);
            if (r0 + 8 < N_NODES)
                *(float2*)&recon[(size_t)(r0 + 8) * DIN + cc] =
                    make_float2(acc[mt][nt][2] + bv.x, acc[mt][nt][3] + bv.y);
        }
    }
}

// ---------------- fused z + d kernel (d emitted as bf16x3 A-matrix) ---------
__global__ void __launch_bounds__(256) zd_kernel(
    const float* __restrict__ emb_W, const float* __restrict__ emb_b,
    const float* __restrict__ dec_W1, const float* __restrict__ dec_b1,
    float* __restrict__ z)
{
    __shared__ float sbuf[10432];
    float (*As)[132] = (float(*)[132])sbuf;
    float (*Bs)[68]  = (float(*)[68])(sbuf + 4224);
    float (*zs)[65]  = (float(*)[65])sbuf;
    float (*W1s)[33] = (float(*)[33])(sbuf + 8320);

    const int t  = threadIdx.x;
    const int tx = t & 15, ty = t >> 4;
    const int m0 = blockIdx.x * 128;

    float acc[8][4];
    #pragma unroll
    for (int i=0;i<8;i++)
        #pragma unroll
        for (int j=0;j<4;j++) acc[i][j]=0.f;

    for (int k0=0;k0<HF;k0+=32) {
        #pragma unroll
        for (int i=0;i<16;i++){
            int lin = t + 256*i;
            int r = lin >> 5, c = lin & 31;
            As[c][r] = (m0+r < N_NODES) ? g_gat[(size_t)(m0+r)*HF + k0+c] : 0.f;
        }
        #pragma unroll
        for (int i=0;i<8;i++){
            int lin = t + 256*i;
            int r = lin >> 6, c = lin & 63;
            Bs[r][c] = emb_W[(size_t)(k0+r)*DEMB + c];
        }
        __syncthreads();
        #pragma unroll
        for (int k=0;k<32;k++){
            float ra[8], rb[4];
            #pragma unroll
            for (int i=0;i<8;i++) ra[i]=As[k][ty*8+i];
            #pragma unroll
            for (int j=0;j<4;j++) rb[j]=Bs[k][tx*4+j];
            #pragma unroll
            for (int i=0;i<8;i++)
                #pragma unroll
                for (int j=0;j<4;j++) acc[i][j] += ra[i]*rb[j];
        }
        __syncthreads();
    }

    const float4 bz = *(const float4*)&emb_b[tx*4];
    #pragma unroll
    for (int i=0;i<8;i++){
        int m = m0 + ty*8 + i;
        float4 v = make_float4(acc[i][0]+bz.x, acc[i][1]+bz.y,
                               acc[i][2]+bz.z, acc[i][3]+bz.w);
        zs[ty*8+i][tx*4+0]=v.x; zs[ty*8+i][tx*4+1]=v.y;
        zs[ty*8+i][tx*4+2]=v.z; zs[ty*8+i][tx*4+3]=v.w;
        if (m < N_NODES) *(float4*)&z[(size_t)m*DEMB + tx*4] = v;
    }
    #pragma unroll
    for (int i=0;i<8;i++){
        int lin = t + 256*i;
        int r = lin >> 5, c = lin & 31;
        W1s[r][c] = dec_W1[(size_t)r*FH + c];
    }
    __syncthreads();

    float acc2[8][2];
    #pragma unroll
    for (int i=0;i<8;i++){ acc2[i][0]=0.f; acc2[i][1]=0.f; }
    #pragma unroll 8
    for (int k=0;k<DEMB;k++){
        float rb0 = W1s[k][tx*2], rb1 = W1s[k][tx*2+1];
        #pragma unroll
        for (int i=0;i<8;i++){
            float ra = zs[ty*8+i][k];
            acc2[i][0] += ra*rb0;
            acc2[i][1] += ra*rb1;
        }
    }
    const float b0 = dec_b1[tx*2], b1 = dec_b1[tx*2+1];
    const int k2 = tx*2;
    #pragma unroll
    for (int i=0;i<8;i++){
        int m = m0 + ty*8 + i;
        if (m < N_NODES){
            float v0 = fmaxf(acc2[i][0]+b0, 0.f);
            float v1 = fmaxf(acc2[i][1]+b1, 0.f);
            __nv_bfloat16 h0 = __float2bfloat16(v0);
            __nv_bfloat16 h1 = __float2bfloat16(v1);
            uint32_t hi2 = (uint32_t)__bfloat16_as_ushort(h0) |
                           ((uint32_t)__bfloat16_as_ushort(h1) << 16);
            uint32_t lo2 = pack_bf16x2(v0 - __bfloat162float(h0),
                                       v1 - __bfloat162float(h1));
            size_t base = (size_t)m * 96;
            *(uint32_t*)&g_dB[base + k2]      = hi2;
            *(uint32_t*)&g_dB[base + 32 + k2] = lo2;
            *(uint32_t*)&g_dB[base + 64 + k2] = hi2;
        }
    }
}

// ---------------- CSR build --------------------------------------------------
__global__ void scan_kernel(){
    __shared__ int sm[1024];
    int t = threadIdx.x;
    const int CH = (N_NODES + 1023)/1024;   // 30
    int base = t*CH;
    int s=0;
    for (int i=0;i<CH;i++){ int idx=base+i; if(idx<N_NODES) s+=g_deg[idx]; }
    sm[t]=s; __syncthreads();
    for (int st=1; st<1024; st<<=1){
        int v = (t>=st)? sm[t-st]:0;
        __syncthreads();
        sm[t]+=v;
        __syncthreads();
    }
    int run = sm[t]-s;
    for (int i=0;i<CH;i++){
        int idx=base+i;
        if (idx<N_NODES){ g_off[idx]=run; g_cur[idx]=run; run+=g_deg[idx]; }
    }
    if (t==1023) g_off[N_NODES]=sm[1023];
}
__global__ void scatter_kernel(const int* __restrict__ ei){
    int e = blockIdx.x*blockDim.x+threadIdx.x;
    if (e<N_EDGES){
        int d = ei[N_EDGES+e];
        int p = atomicAdd(&g_cur[d],1);
        g_srcs[p] = ei[e];
    }
}

// ---------------- softmax + aggregate: warp per node ------------------------
// lane l covers feature h*32+l of every head h; lanes 0-7 compute p per head.
__global__ void __launch_bounds__(256) agg_kernel(const float* __restrict__ bias_gat)
{
    const int wid  = threadIdx.x >> 5;
    const int lane = threadIdx.x & 31;
    const int node = blockIdx.x * 8 + wid;
    if (node >= N_NODES) return;

    const int off = g_off[node];
    const int deg = g_off[node + 1] - off;

    float adv = 0.f, den = 0.f, pv = 0.f;
    if (lane < NH) {
        adv = g_ad[node * NH + lane];
        float l = g_as[node * NH + lane] + adv;
        l = (l > 0.f) ? l : NEG * l;
        pv = expf(l);
        den = pv;
    }

    const float* hrow = g_h + (size_t)node * HF;
    float acc[NH];
    #pragma unroll
    for (int h = 0; h < NH; h++)
        acc[h] = hrow[h * FH + lane] * __shfl_sync(0xffffffffu, pv, h);

    for (int e = 0; e < deg; e++) {
        const int s = g_srcs[off + e];
        float pe = 0.f;
        if (lane < NH) {
            float l = g_as[s * NH + lane] + adv;
            l = (l > 0.f) ? l : NEG * l;
            pe = expf(l);
            den += pe;
        }
        const float* srow = g_h + (size_t)s * HF;
        #pragma unroll
        for (int h = 0; h < NH; h++)
            acc[h] += srow[h * FH + lane] * __shfl_sync(0xffffffffu, pe, h);
    }

    #pragma unroll
    for (int h = 0; h < NH; h++) {
        const float d = __shfl_sync(0xffffffffu, den, h);
        const float v = acc[h] / d + bias_gat[h * FH + lane];
        g_gat[(size_t)node * HF + h * FH + lane] = fmaxf(v, 0.f);
    }
}

// ---------------- launch -----------------------------------------------------
extern "C" void kernel_launch(void* const* d_in, const int* in_sizes, int n_in,
                              void* d_out, int out_size)
{
    const float* x        = (const float*)d_in[0];
    const int*   ei       = (const int*)  d_in[1];
    const float* W        = (const float*)d_in[3];
    const float* att_src  = (const float*)d_in[4];
    const float* att_dst  = (const float*)d_in[5];
    const float* bias_gat = (const float*)d_in[6];
    const float* emb_W    = (const float*)d_in[7];
    const float* emb_b    = (const float*)d_in[8];
    const float* dec_W1   = (const float*)d_in[9];
    const float* dec_b1   = (const float*)d_in[10];
    const float* dec_W2   = (const float*)d_in[11];
    const float* dec_b2   = (const float*)d_in[12];

    float* recon = (float*)d_out;                              // [N, DIN]
    float* z     = (float*)d_out + (size_t)N_NODES*DIN;        // [N, DEMB]

    cudaFuncSetAttribute(gemm1_mma_kernel,
                         cudaFuncAttributeMaxDynamicSharedMemorySize, GSMT);
    cudaFuncSetAttribute(recon_mma_kernel,
                         cudaFuncAttributeMaxDynamicSharedMemorySize, RSMT);

    const int MB = (N_NODES + 127)/128;   // 235

    // 0) operand prep (split zeroes g_deg; build_wB counts degrees + packs W,W2)
    split_x_kernel<<<(int)(((size_t)N_PAD*KSEC/8 + 255)/256), 256>>>(x);
    build_wB_kernel<<<(HF*KTOT + 255)/256, 256>>>(W, dec_W2, ei);
    // 1) h = x @ W via mma.sync bf16x3 (+ fused a_s/a_d)
    gemm1_mma_kernel<<<dim3(2, MB), 256, GSMT>>>(att_src, att_dst);
    // 2) CSR finish
    scan_kernel   <<<1,1024>>>();
    scatter_kernel<<<(N_EDGES+255)/256,256>>>(ei);
    // 3) attention softmax + aggregate + bias + relu (warp per node)
    agg_kernel<<<(N_NODES+7)/8, 256>>>(bias_gat);
    // 4+5) fused z and d (d emitted as bf16x3)
    zd_kernel<<<MB, 256>>>(emb_W, emb_b, dec_W1, dec_b1, z);
    // 6) recon = d @ dec_W2 + dec_b2 via mma.sync bf16x3
    recon_mma_kernel<<<dim3(8, MB), 256, RSMT>>>(dec_b2, recon);
}